// round 6
// baseline (speedup 1.0000x reference)
#include <cuda_runtime.h>
#include <cuda_fp16.h>

#define Bq 8
#define Sq 1024
#define Dm 1024
#define NH 16
#define DH 64

#define TS  72     // half tile row stride (144B -> +4 banks/row, LDSM conflict-free)
#define SLOT (64 * TS)          // one 64-key x 64-dh half tile
#define SCL 0.18033688011112043f  // 0.125 * log2(e)

// ---- scratch (device globals: allocation-free rule) ----
__device__ __half g_Hh[(size_t)Bq*Sq*Dm];
__device__ __half g_Q[(size_t)Bq*NH*Sq*DH];
__device__ __half g_K[(size_t)Bq*NH*Sq*DH];
__device__ __half g_V[(size_t)Bq*NH*Sq*DH];
__device__ __half g_heads[(size_t)Bq*Sq*Dm];
__device__ __half g_Woh[(size_t)Dm*Dm];

// ---- helpers ----
__device__ __forceinline__ void mma_f16(float c[4], const unsigned a[4],
                                        unsigned b0, unsigned b1) {
    asm volatile(
        "mma.sync.aligned.m16n8k16.row.col.f32.f16.f16.f32 "
        "{%0,%1,%2,%3}, {%4,%5,%6,%7}, {%8,%9}, {%0,%1,%2,%3};"
        : "+f"(c[0]), "+f"(c[1]), "+f"(c[2]), "+f"(c[3])
        : "r"(a[0]), "r"(a[1]), "r"(a[2]), "r"(a[3]), "r"(b0), "r"(b1));
}
__device__ __forceinline__ unsigned sptr(const void* p) {
    return (unsigned)__cvta_generic_to_shared(p);
}
__device__ __forceinline__ void ldm_x4(unsigned r[4], unsigned addr) {
    asm volatile("ldmatrix.sync.aligned.m8n8.x4.shared.b16 {%0,%1,%2,%3}, [%4];"
                 : "=r"(r[0]), "=r"(r[1]), "=r"(r[2]), "=r"(r[3]) : "r"(addr));
}
__device__ __forceinline__ void ldm_x4_t(unsigned r[4], unsigned addr) {
    asm volatile("ldmatrix.sync.aligned.m8n8.x4.trans.shared.b16 {%0,%1,%2,%3}, [%4];"
                 : "=r"(r[0]), "=r"(r[1]), "=r"(r[2]), "=r"(r[3]) : "r"(addr));
}
__device__ __forceinline__ void cpa16(unsigned dst, const void* src) {
    asm volatile("cp.async.cg.shared.global [%0], [%1], 16;" :: "r"(dst), "l"(src));
}
#define CPA_COMMIT() asm volatile("cp.async.commit_group;")
#define CPA_WAIT(n)  asm volatile("cp.async.wait_group %0;" :: "n"(n))
__device__ __forceinline__ float ex2f(float x) {
    float y;
    asm("ex2.approx.f32 %0, %1;" : "=f"(y) : "f"(x));
    return y;
}

// ============================================================================
// K0a: Wo f32 -> half.  K0b: H f32 -> half.
// ============================================================================
__global__ void wconv_kernel(const float* __restrict__ Wo) {
    int i = (blockIdx.x * 256 + threadIdx.x) * 4;
    float4 v = *(const float4*)&Wo[i];
    __half2* dst = (__half2*)&g_Woh[i];
    dst[0] = __floats2half2_rn(v.x, v.y);
    dst[1] = __floats2half2_rn(v.z, v.w);
}
__global__ void hconv_kernel(const float* __restrict__ H) {
    int i = (blockIdx.x * 256 + threadIdx.x) * 4;
    float4 v = *(const float4*)&H[i];
    __half2* dst = (__half2*)&g_Hh[i];
    dst[0] = __floats2half2_rn(v.x, v.y);
    dst[1] = __floats2half2_rn(v.z, v.w);
}

// ============================================================================
// K1: fused QKV projection, fp16 mma + ldmatrix. grid (64, NH), 256 thr.
// ============================================================================
__global__ void __launch_bounds__(256) qkv_kernel(
    const float* __restrict__ Wq, const float* __restrict__ bq,
    const float* __restrict__ Wk, const float* __restrict__ bk,
    const float* __restrict__ Wv, const float* __restrict__ bv)
{
    extern __shared__ __half hsm[];
    __half* Hs = hsm;               // 128 x 72
    __half* Ws = hsm + 128 * TS;    // 3 x 64 x 72

    const int tid  = threadIdx.x;
    const int lane = tid & 31;
    const int warp = tid >> 5;
    const int g = lane >> 3, rr = lane & 7;
    const int warpM = warp >> 1;   // 0..3: 32 rows
    const int warpN = warp & 1;    // 0..1: 32 cols
    const int h    = blockIdx.y;
    const int row0 = blockIdx.x * 128;
    const int b    = row0 >> 10;
    const int s    = row0 & 1023;

    for (int i = tid; i < 128 * 8; i += 256) {
        int r = i >> 3, q = i & 7;
        cpa16(sptr(&Hs[r * TS + q * 8]),
              g_Hh + (size_t)(row0 + r) * Dm + h * DH + q * 8);
    }
    CPA_COMMIT();

    const float* Wt[3] = {Wq, Wk, Wv};
    for (int wsel = 0; wsel < 3; wsel++) {
        const float* W = Wt[wsel] + h * DH * DH;
        __half* Wd = Ws + wsel * 64 * TS;
        for (int i = tid; i < 64 * 16; i += 256) {
            int r = i >> 4, q = i & 15;
            float4 v = *(const float4*)&W[r * DH + q * 4];
            __half2* dst = (__half2*)&Wd[r * TS + q * 4];
            dst[0] = __floats2half2_rn(v.x, v.y);
            dst[1] = __floats2half2_rn(v.z, v.w);
        }
    }
    CPA_WAIT(0);
    __syncthreads();

    unsigned a[4][2][4];
    #pragma unroll
    for (int ks = 0; ks < 4; ks++)
        #pragma unroll
        for (int mi = 0; mi < 2; mi++) {
            int row = warpM * 32 + mi * 16 + rr + (g & 1) * 8;
            int col = ks * 16 + (g >> 1) * 8;
            ldm_x4(a[ks][mi], sptr(&Hs[row * TS + col]));
        }

    const float* bt[3] = {bq, bk, bv};
    __half*      Ot[3] = {g_Q, g_K, g_V};

    #pragma unroll
    for (int wsel = 0; wsel < 3; wsel++) {
        const __half* Wd = Ws + wsel * 64 * TS;
        float c[2][4][4];
        #pragma unroll
        for (int mi = 0; mi < 2; mi++)
            #pragma unroll
            for (int t = 0; t < 4; t++)
                #pragma unroll
                for (int q = 0; q < 4; q++) c[mi][t][q] = 0.f;

        #pragma unroll
        for (int ks = 0; ks < 4; ks++) {
            #pragma unroll
            for (int hn = 0; hn < 2; hn++) {
                int row = warpN * 32 + hn * 16 + rr + (g >> 1) * 8;
                int col = ks * 16 + (g & 1) * 8;
                unsigned bb[4];
                ldm_x4(bb, sptr(&Wd[row * TS + col]));
                #pragma unroll
                for (int mi = 0; mi < 2; mi++) {
                    mma_f16(c[mi][hn * 2 + 0], a[ks][mi], bb[0], bb[1]);
                    mma_f16(c[mi][hn * 2 + 1], a[ks][mi], bb[2], bb[3]);
                }
            }
        }

        const float* bias = bt[wsel] + h * DH;
        __half* O = Ot[wsel] + ((size_t)(b * NH + h) * Sq + s) * DH;
        #pragma unroll
        for (int mi = 0; mi < 2; mi++)
            #pragma unroll
            for (int t = 0; t < 4; t++) {
                int r  = warpM * 32 + mi * 16 + (lane >> 2);
                int cN = warpN * 32 + t * 8 + (lane & 3) * 2;
                float b0v = bias[cN], b1v = bias[cN + 1];
                *(__half2*)&O[(size_t)r * DH + cN] =
                    __floats2half2_rn(c[mi][t][0] + b0v, c[mi][t][1] + b1v);
                *(__half2*)&O[(size_t)(r + 8) * DH + cN] =
                    __floats2half2_rn(c[mi][t][2] + b0v, c[mi][t][3] + b1v);
            }
    }
}

// ============================================================================
// K2: attention, two-pass recompute, NO score buffer.
// Block = 128 query rows, 8 warps (16 rows each, full key sweep), 256 thr.
// Pass 1: QK^T tiles -> mask -> ex2 -> row-sum Z (registers only).
// Pass 2: recompute QK^T -> normalize -> A straight from regs -> P@V.
// grid (NH, 8, Bq) h-fastest. 72KB smem -> 2 CTAs/SM.
// ============================================================================
__global__ void __launch_bounds__(256, 2) attn_kernel(
    const int* __restrict__ mask, float* __restrict__ Aout)
{
    extern __shared__ __half hsm[];
    __half* Qs = hsm;               // 128 x 72
    __half* KV = hsm + 128 * TS;    // 6 slots x 64 x 72

    const int tid = threadIdx.x, lane = tid & 31, warp = tid >> 5;
    const int h = blockIdx.x, b = blockIdx.z, s0 = blockIdx.y * 128;
    const int g = lane >> 3, rr = lane & 7;
    const int qr = lane >> 2;                 // row within 8-group
    const int row = warp * 16 + qr;           // local query row (and +8)

    const __half* Qg = g_Q + ((size_t)(b * NH + h) * Sq + s0) * DH;
    const __half* Kg = g_K + (size_t)(b * NH + h) * Sq * DH;
    const __half* Vg = g_V + (size_t)(b * NH + h) * Sq * DH;

    const int* mr0 = mask + ((size_t)b * Sq + s0 + row) * Sq;
    const int* mr1 = mr0 + 8 * Sq;
    float* Ar0 = Aout + (((size_t)h * Bq + b) * Sq + s0 + row) * Sq;
    float* Ar1 = Ar0 + 8 * Sq;

    auto issueK = [&](int t) {
        __half* dst = KV + (t & 3) * SLOT;
        const __half* src = Kg + (size_t)t * 64 * DH;
        for (int i = tid; i < 64 * 8; i += 256) {
            int r = i >> 3, q = i & 7;
            cpa16(sptr(&dst[r * TS + q * 8]), src + (size_t)r * DH + q * 8);
        }
        CPA_COMMIT();
    };
    auto issueKV = [&](int t) {
        int p = t % 3;
        __half* dk = KV + (2 * p) * SLOT;
        __half* dv = KV + (2 * p + 1) * SLOT;
        const __half* sk = Kg + (size_t)t * 64 * DH;
        const __half* sv = Vg + (size_t)t * 64 * DH;
        for (int i = tid; i < 64 * 8; i += 256) {
            int r = i >> 3, q = i & 7;
            cpa16(sptr(&dk[r * TS + q * 8]), sk + (size_t)r * DH + q * 8);
            cpa16(sptr(&dv[r * TS + q * 8]), sv + (size_t)r * DH + q * 8);
        }
        CPA_COMMIT();
    };

    // prologue: K0..K2 + Q tile
    issueK(0); issueK(1); issueK(2);
    for (int i = tid; i < 128 * 8; i += 256) {
        int r = i >> 3, q = i & 7;
        *(uint4*)&Qs[r * TS + q * 8] = ((const uint4*)Qg)[r * 8 + q];
    }
    __syncthreads();

    // Q fragments, loop-invariant
    unsigned qa[4][4];
    #pragma unroll
    for (int ks = 0; ks < 4; ks++)
        ldm_x4(qa[ks], sptr(&Qs[(warp * 16 + rr + (g & 1) * 8) * TS +
                                ks * 16 + (g >> 1) * 8]));

    // ================= PASS 1: row sums =================
    float Z0 = 0.f, Z1 = 0.f;
    #pragma unroll 1
    for (int t = 0; t < 16; t++) {
        if (t <= 13) CPA_WAIT(2);
        else if (t == 14) CPA_WAIT(1);
        else CPA_WAIT(0);
        __syncthreads();
        if (t + 3 < 16) issueK(t + 3);   // slot (t-1)&3: reads done before this sync
        const __half* Kt = KV + (t & 3) * SLOT;

        float c[8][4];
        #pragma unroll
        for (int nt = 0; nt < 8; nt++)
            #pragma unroll
            for (int q = 0; q < 4; q++) c[nt][q] = 0.f;

        #pragma unroll
        for (int ks = 0; ks < 4; ks++)
            #pragma unroll
            for (int n2 = 0; n2 < 4; n2++) {
                unsigned bb[4];
                ldm_x4(bb, sptr(&Kt[(n2 * 16 + rr + (g >> 1) * 8) * TS +
                                    ks * 16 + (g & 1) * 8]));
                mma_f16(c[n2 * 2 + 0], qa[ks], bb[0], bb[1]);
                mma_f16(c[n2 * 2 + 1], qa[ks], bb[2], bb[3]);
            }

        #pragma unroll
        for (int nt = 0; nt < 8; nt++) {
            int jc = t * 64 + nt * 8 + (lane & 3) * 2;
            int2 ma = *(const int2*)(mr0 + jc);
            int2 mb = *(const int2*)(mr1 + jc);
            Z0 += (ma.x ? ex2f(c[nt][0] * SCL) : 0.f)
                + (ma.y ? ex2f(c[nt][1] * SCL) : 0.f);
            Z1 += (mb.x ? ex2f(c[nt][2] * SCL) : 0.f)
                + (mb.y ? ex2f(c[nt][3] * SCL) : 0.f);
        }
    }
    // quad reduce (lanes sharing the same row)
    Z0 += __shfl_xor_sync(~0u, Z0, 1); Z0 += __shfl_xor_sync(~0u, Z0, 2);
    Z1 += __shfl_xor_sync(~0u, Z1, 1); Z1 += __shfl_xor_sync(~0u, Z1, 2);
    const float invZ0 = 1.0f / Z0, invZ1 = 1.0f / Z1;

    __syncthreads();   // all pass-1 reads done before pass-2 slot reuse
    issueKV(0); issueKV(1);

    // ================= PASS 2: A + P@V =================
    float o[8][4];
    #pragma unroll
    for (int nt = 0; nt < 8; nt++)
        #pragma unroll
        for (int q = 0; q < 4; q++) o[nt][q] = 0.f;

    #pragma unroll 1
    for (int t = 0; t < 16; t++) {
        if (t < 15) CPA_WAIT(1);
        else CPA_WAIT(0);
        __syncthreads();
        if (t + 2 < 16) issueKV(t + 2);  // pair (t-1)%3: reads done before this sync
        const __half* Kt = KV + (2 * (t % 3)) * SLOT;
        const __half* Vt = Kt + SLOT;

        float c[8][4];
        #pragma unroll
        for (int nt = 0; nt < 8; nt++)
            #pragma unroll
            for (int q = 0; q < 4; q++) c[nt][q] = 0.f;

        #pragma unroll
        for (int ks = 0; ks < 4; ks++)
            #pragma unroll
            for (int n2 = 0; n2 < 4; n2++) {
                unsigned bb[4];
                ldm_x4(bb, sptr(&Kt[(n2 * 16 + rr + (g >> 1) * 8) * TS +
                                    ks * 16 + (g & 1) * 8]));
                mma_f16(c[n2 * 2 + 0], qa[ks], bb[0], bb[1]);
                mma_f16(c[n2 * 2 + 1], qa[ks], bb[2], bb[3]);
            }

        unsigned pf[8][2];
        #pragma unroll
        for (int nt = 0; nt < 8; nt++) {
            int jc = t * 64 + nt * 8 + (lane & 3) * 2;
            int2 ma = *(const int2*)(mr0 + jc);
            int2 mb = *(const int2*)(mr1 + jc);
            float p00 = ma.x ? ex2f(c[nt][0] * SCL) * invZ0 : 0.f;
            float p01 = ma.y ? ex2f(c[nt][1] * SCL) * invZ0 : 0.f;
            float p10 = mb.x ? ex2f(c[nt][2] * SCL) * invZ1 : 0.f;
            float p11 = mb.y ? ex2f(c[nt][3] * SCL) * invZ1 : 0.f;
            __stcs((float2*)(Ar0 + jc), make_float2(p00, p01));
            __stcs((float2*)(Ar1 + jc), make_float2(p10, p11));
            __half2 h0 = __floats2half2_rn(p00, p01);
            __half2 h1 = __floats2half2_rn(p10, p11);
            pf[nt][0] = *(unsigned*)&h0;
            pf[nt][1] = *(unsigned*)&h1;
        }

        // P@V: C-frag layout == A-frag layout (FA2 identity)
        #pragma unroll
        for (int ks = 0; ks < 4; ks++) {
            unsigned a[4] = {pf[2 * ks][0], pf[2 * ks][1],
                             pf[2 * ks + 1][0], pf[2 * ks + 1][1]};
            #pragma unroll
            for (int vt = 0; vt < 4; vt++) {
                unsigned bb[4];
                ldm_x4_t(bb, sptr(&Vt[(ks * 16 + rr + (g & 1) * 8) * TS +
                                      vt * 16 + (g >> 1) * 8]));
                mma_f16(o[vt * 2 + 0], a, bb[0], bb[1]);
                mma_f16(o[vt * 2 + 1], a, bb[2], bb[3]);
            }
        }
    }

    // write heads (normalized already)
    {
        size_t base = ((size_t)(b * Sq + s0 + row)) * Dm + h * DH;
        #pragma unroll
        for (int nt = 0; nt < 8; nt++) {
            int cN = nt * 8 + (lane & 3) * 2;
            *(__half2*)&g_heads[base + cN] = __floats2half2_rn(o[nt][0], o[nt][1]);
            *(__half2*)&g_heads[base + 8 * Dm + cN] = __floats2half2_rn(o[nt][2], o[nt][3]);
        }
    }
}

// ============================================================================
// K3: out = heads @ Woh^T + bo. fp16 mma, tile 128x128, cp.async 2-stage.
// grid (64, 8), 256 thr.
// ============================================================================
__global__ void __launch_bounds__(256) out_kernel(
    const float* __restrict__ bo, float* __restrict__ out)
{
    extern __shared__ __half hsm[];
    __half* As = hsm;                  // 2 x 128 x 72
    __half* Bs = hsm + 2 * 128 * TS;   // 2 x 128 x 72

    const int tid = threadIdx.x, lane = tid & 31, warp = tid >> 5;
    const int g = lane >> 3, rr = lane & 7;
    const int warpM = warp >> 2;
    const int warpN = warp & 3;
    const int r0 = blockIdx.x * 128, n0 = blockIdx.y * 128;

    auto issue = [&](int kt, int buf) {
        __half* ad = As + buf * 128 * TS;
        __half* bd = Bs + buf * 128 * TS;
        const __half* as = g_heads + (size_t)r0 * Dm + kt * 64;
        const __half* bs = g_Woh   + (size_t)n0 * Dm + kt * 64;
        for (int i = tid; i < 128 * 8; i += 256) {
            int r = i >> 3, q = i & 7;
            cpa16(sptr(&ad[r * TS + q * 8]), as + (size_t)r * Dm + q * 8);
        }
        for (int i = tid; i < 128 * 8; i += 256) {
            int r = i >> 3, q = i & 7;
            cpa16(sptr(&bd[r * TS + q * 8]), bs + (size_t)r * Dm + q * 8);
        }
        CPA_COMMIT();
    };

    float c[4][4][4];
    #pragma unroll
    for (int mi = 0; mi < 4; mi++)
        #pragma unroll
        for (int nt = 0; nt < 4; nt++)
            #pragma unroll
            for (int q = 0; q < 4; q++) c[mi][nt][q] = 0.f;

    issue(0, 0);

    for (int kt = 0; kt < 16; kt++) {
        if (kt < 15) { issue(kt + 1, (kt + 1) & 1); CPA_WAIT(1); }
        else         { CPA_WAIT(0); }
        __syncthreads();
        const __half* At = As + (kt & 1) * 128 * TS;
        const __half* Bt = Bs + (kt & 1) * 128 * TS;

        #pragma unroll
        for (int ks = 0; ks < 4; ks++) {
            int k0 = ks * 16;
            unsigned a[4][4];
            #pragma unroll
            for (int mi = 0; mi < 4; mi++) {
                int row = warpM * 64 + mi * 16 + rr + (g & 1) * 8;
                int col = k0 + (g >> 1) * 8;
                ldm_x4(a[mi], sptr(&At[row * TS + col]));
            }
            unsigned bb[2][4];
            #pragma unroll
            for (int hn = 0; hn < 2; hn++) {
                int row = warpN * 32 + hn * 16 + rr + (g >> 1) * 8;
                int col = k0 + (g & 1) * 8;
                ldm_x4(bb[hn], sptr(&Bt[row * TS + col]));
            }
            #pragma unroll
            for (int mi = 0; mi < 4; mi++) {
                mma_f16(c[mi][0], a[mi], bb[0][0], bb[0][1]);
                mma_f16(c[mi][1], a[mi], bb[0][2], bb[0][3]);
                mma_f16(c[mi][2], a[mi], bb[1][0], bb[1][1]);
                mma_f16(c[mi][3], a[mi], bb[1][2], bb[1][3]);
            }
        }
        __syncthreads();
    }

    #pragma unroll
    for (int mi = 0; mi < 4; mi++) {
        #pragma unroll
        for (int nt = 0; nt < 4; nt++) {
            int r  = r0 + warpM * 64 + mi * 16 + (lane >> 2);
            int cN = n0 + warpN * 32 + nt * 8 + (lane & 3) * 2;
            float b0v = bo[cN], b1v = bo[cN + 1];
            out[(size_t)r * Dm + cN]           = c[mi][nt][0] + b0v;
            out[(size_t)r * Dm + cN + 1]       = c[mi][nt][1] + b1v;
            out[(size_t)(r + 8) * Dm + cN]     = c[mi][nt][2] + b0v;
            out[(size_t)(r + 8) * Dm + cN + 1] = c[mi][nt][3] + b1v;
        }
    }
}

// ============================================================================
extern "C" void kernel_launch(void* const* d_in, const int* in_sizes, int n_in,
                              void* d_out, int out_size)
{
    const float* H    = (const float*)d_in[0];
    const int*   mask = (const int*)  d_in[1];
    const float* Wq   = (const float*)d_in[2];
    const float* bq   = (const float*)d_in[3];
    const float* Wk   = (const float*)d_in[4];
    const float* bk   = (const float*)d_in[5];
    const float* Wv   = (const float*)d_in[6];
    const float* bv   = (const float*)d_in[7];
    const float* Wo   = (const float*)d_in[8];
    const float* bo   = (const float*)d_in[9];

    float* out  = (float*)d_out;
    float* Aout = out + (size_t)Bq * Sq * Dm;

    const int smem1 = (128 * TS + 3 * 64 * TS) * sizeof(__half);   // 46080
    const int smem2 = (128 * TS + 6 * SLOT) * sizeof(__half);      // 73728
    const int smem3 = 4 * 128 * TS * sizeof(__half);               // 73728

    cudaFuncSetAttribute(qkv_kernel,  cudaFuncAttributeMaxDynamicSharedMemorySize, smem1);
    cudaFuncSetAttribute(attn_kernel, cudaFuncAttributeMaxDynamicSharedMemorySize, smem2);
    cudaFuncSetAttribute(out_kernel,  cudaFuncAttributeMaxDynamicSharedMemorySize, smem3);

    wconv_kernel<<<1024, 256>>>(Wo);
    hconv_kernel<<<8192, 256>>>(H);
    qkv_kernel<<<dim3(64, NH), 256, smem1>>>(Wq, bq, Wk, bk, Wv, bv);
    attn_kernel<<<dim3(NH, 8, Bq), 256, smem2>>>(mask, Aout);
    out_kernel<<<dim3(64, 8), 256, smem3>>>(bo, out);
}

// round 7
// speedup vs baseline: 1.1758x; 1.1758x over previous
#include <cuda_runtime.h>
#include <cuda_fp16.h>

#define Bq 8
#define Sq 1024
#define Dm 1024
#define NH 16
#define DH 64

#define PSH 1032   // half score/P row stride (2064B: +4 banks/row, LDSM conflict-free)
#define TS  72     // half tile row stride (144B: +4 banks/row)
#define SCL 0.18033688011112043f  // 0.125 * log2(e)

// ---- scratch (device globals: allocation-free rule) ----
__device__ __half g_Hh[(size_t)Bq*Sq*Dm];
__device__ __half g_Q[(size_t)Bq*NH*Sq*DH];
__device__ __half g_K[(size_t)Bq*NH*Sq*DH];
__device__ __half g_V[(size_t)Bq*NH*Sq*DH];
__device__ __half g_heads[(size_t)Bq*Sq*Dm];
__device__ __half g_Woh[(size_t)Dm*Dm];

// ---- helpers ----
__device__ __forceinline__ void mma_f16(float c[4], const unsigned a[4],
                                        unsigned b0, unsigned b1) {
    asm volatile(
        "mma.sync.aligned.m16n8k16.row.col.f32.f16.f16.f32 "
        "{%0,%1,%2,%3}, {%4,%5,%6,%7}, {%8,%9}, {%0,%1,%2,%3};"
        : "+f"(c[0]), "+f"(c[1]), "+f"(c[2]), "+f"(c[3])
        : "r"(a[0]), "r"(a[1]), "r"(a[2]), "r"(a[3]), "r"(b0), "r"(b1));
}
__device__ __forceinline__ unsigned sptr(const void* p) {
    return (unsigned)__cvta_generic_to_shared(p);
}
__device__ __forceinline__ void ldm_x4(unsigned r[4], unsigned addr) {
    asm volatile("ldmatrix.sync.aligned.m8n8.x4.shared.b16 {%0,%1,%2,%3}, [%4];"
                 : "=r"(r[0]), "=r"(r[1]), "=r"(r[2]), "=r"(r[3]) : "r"(addr));
}
__device__ __forceinline__ void ldm_x2_t(unsigned r[2], unsigned addr) {
    asm volatile("ldmatrix.sync.aligned.m8n8.x2.trans.shared.b16 {%0,%1}, [%2];"
                 : "=r"(r[0]), "=r"(r[1]) : "r"(addr));
}
__device__ __forceinline__ void cpa16(unsigned dst, const void* src) {
    asm volatile("cp.async.cg.shared.global [%0], [%1], 16;" :: "r"(dst), "l"(src));
}
#define CPA_COMMIT() asm volatile("cp.async.commit_group;")
#define CPA_WAIT(n)  asm volatile("cp.async.wait_group %0;" :: "n"(n))
__device__ __forceinline__ float ex2f(float x) {
    float y;
    asm("ex2.approx.f32 %0, %1;" : "=f"(y) : "f"(x));
    return y;
}

// ============================================================================
// K0a: Wo f32 -> half.  K0b: H f32 -> half.
// ============================================================================
__global__ void wconv_kernel(const float* __restrict__ Wo) {
    int i = (blockIdx.x * 256 + threadIdx.x) * 4;
    float4 v = *(const float4*)&Wo[i];
    __half2* dst = (__half2*)&g_Woh[i];
    dst[0] = __floats2half2_rn(v.x, v.y);
    dst[1] = __floats2half2_rn(v.z, v.w);
}
__global__ void hconv_kernel(const float* __restrict__ H) {
    int i = (blockIdx.x * 256 + threadIdx.x) * 4;
    float4 v = *(const float4*)&H[i];
    __half2* dst = (__half2*)&g_Hh[i];
    dst[0] = __floats2half2_rn(v.x, v.y);
    dst[1] = __floats2half2_rn(v.z, v.w);
}

// ============================================================================
// K1: fused QKV projection, fp16 mma + ldmatrix. grid (64, NH), 256 thr.
// ============================================================================
__global__ void __launch_bounds__(256) qkv_kernel(
    const float* __restrict__ Wq, const float* __restrict__ bq,
    const float* __restrict__ Wk, const float* __restrict__ bk,
    const float* __restrict__ Wv, const float* __restrict__ bv)
{
    extern __shared__ __half hsm[];
    __half* Hs = hsm;               // 128 x 72
    __half* Ws = hsm + 128 * TS;    // 3 x 64 x 72

    const int tid  = threadIdx.x;
    const int lane = tid & 31;
    const int warp = tid >> 5;
    const int g = lane >> 3, rr = lane & 7;
    const int warpM = warp >> 1;   // 0..3: 32 rows
    const int warpN = warp & 1;    // 0..1: 32 cols
    const int h    = blockIdx.y;
    const int row0 = blockIdx.x * 128;
    const int b    = row0 >> 10;
    const int s    = row0 & 1023;

    for (int i = tid; i < 128 * 8; i += 256) {
        int r = i >> 3, q = i & 7;
        cpa16(sptr(&Hs[r * TS + q * 8]),
              g_Hh + (size_t)(row0 + r) * Dm + h * DH + q * 8);
    }
    CPA_COMMIT();

    const float* Wt[3] = {Wq, Wk, Wv};
    for (int wsel = 0; wsel < 3; wsel++) {
        const float* W = Wt[wsel] + h * DH * DH;
        __half* Wd = Ws + wsel * 64 * TS;
        for (int i = tid; i < 64 * 16; i += 256) {
            int r = i >> 4, q = i & 15;
            float4 v = *(const float4*)&W[r * DH + q * 4];
            __half2* dst = (__half2*)&Wd[r * TS + q * 4];
            dst[0] = __floats2half2_rn(v.x, v.y);
            dst[1] = __floats2half2_rn(v.z, v.w);
        }
    }
    CPA_WAIT(0);
    __syncthreads();

    unsigned a[4][2][4];
    #pragma unroll
    for (int ks = 0; ks < 4; ks++)
        #pragma unroll
        for (int mi = 0; mi < 2; mi++) {
            int row = warpM * 32 + mi * 16 + rr + (g & 1) * 8;
            int col = ks * 16 + (g >> 1) * 8;
            ldm_x4(a[ks][mi], sptr(&Hs[row * TS + col]));
        }

    const float* bt[3] = {bq, bk, bv};
    __half*      Ot[3] = {g_Q, g_K, g_V};

    #pragma unroll
    for (int wsel = 0; wsel < 3; wsel++) {
        const __half* Wd = Ws + wsel * 64 * TS;
        float c[2][4][4];
        #pragma unroll
        for (int mi = 0; mi < 2; mi++)
            #pragma unroll
            for (int t = 0; t < 4; t++)
                #pragma unroll
                for (int q = 0; q < 4; q++) c[mi][t][q] = 0.f;

        #pragma unroll
        for (int ks = 0; ks < 4; ks++) {
            #pragma unroll
            for (int hn = 0; hn < 2; hn++) {
                int row = warpN * 32 + hn * 16 + rr + (g >> 1) * 8;
                int col = ks * 16 + (g & 1) * 8;
                unsigned bb[4];
                ldm_x4(bb, sptr(&Wd[row * TS + col]));
                #pragma unroll
                for (int mi = 0; mi < 2; mi++) {
                    mma_f16(c[mi][hn * 2 + 0], a[ks][mi], bb[0], bb[1]);
                    mma_f16(c[mi][hn * 2 + 1], a[ks][mi], bb[2], bb[3]);
                }
            }
        }

        const float* bias = bt[wsel] + h * DH;
        __half* O = Ot[wsel] + ((size_t)(b * NH + h) * Sq + s) * DH;
        #pragma unroll
        for (int mi = 0; mi < 2; mi++)
            #pragma unroll
            for (int t = 0; t < 4; t++) {
                int r  = warpM * 32 + mi * 16 + (lane >> 2);
                int cN = warpN * 32 + t * 8 + (lane & 3) * 2;
                float b0v = bias[cN], b1v = bias[cN + 1];
                *(__half2*)&O[(size_t)r * DH + cN] =
                    __floats2half2_rn(c[mi][t][0] + b0v, c[mi][t][1] + b1v);
                *(__half2*)&O[(size_t)(r + 8) * DH + cN] =
                    __floats2half2_rn(c[mi][t][2] + b0v, c[mi][t][3] + b1v);
            }
    }
}

// ============================================================================
// K2: attention, single-pass (R3 structure), 512 thr / 16 warps, 2 CTAs/SM.
// 32 query rows per block; phase A: warp = 16 rows x 16 keys; phase B:
// warp = 16 rows x 8 head-cols. Softmax: 2 rows/warp, smem sweeps (no reg cache).
// grid (NH, 32, Bq) h-fastest.
// ============================================================================
__global__ void __launch_bounds__(512, 2) attn_kernel(
    const int* __restrict__ mask, float* __restrict__ Aout)
{
    extern __shared__ __half hsm[];
    __half* psh = hsm;               // 32 x 1032 (scores -> exp -> P)
    __half* Qs  = psh + 32 * PSH;    // 32 x 72
    __half* KV  = Qs + 32 * TS;      // 2 x 128 x 72

    const int tid = threadIdx.x, lane = tid & 31, warp = tid >> 5;
    const int h = blockIdx.x, b = blockIdx.z, s0 = blockIdx.y * 32;
    const int g = lane >> 3, rr = lane & 7;
    const int warpM = warp >> 3;     // 0..1: 16 rows
    const int wn    = warp & 7;      // 0..7

    const __half* Qg = g_Q + ((size_t)(b * NH + h) * Sq + s0) * DH;
    const __half* Kg = g_K + (size_t)(b * NH + h) * Sq * DH;
    const __half* Vg = g_V + (size_t)(b * NH + h) * Sq * DH;

    auto issue = [&](const __half* src, int buf) {
        __half* dst = KV + buf * 128 * TS;
        for (int i = tid; i < 128 * 8; i += 512) {
            int r = i >> 3, q = i & 7;
            cpa16(sptr(&dst[r * TS + q * 8]), src + (size_t)r * DH + q * 8);
        }
        CPA_COMMIT();
    };

    issue(Kg, 0);
    for (int i = tid; i < 32 * 8; i += 512) {
        int r = i >> 3, q = i & 7;
        *(uint4*)&Qs[r * TS + q * 8] = ((const uint4*)Qg)[r * 8 + q];
    }
    __syncthreads();

    // Q fragments (loop-invariant)
    unsigned qa[4][4];
    #pragma unroll
    for (int ks = 0; ks < 4; ks++)
        ldm_x4(qa[ks], sptr(&Qs[(warpM * 16 + rr + (g & 1) * 8) * TS +
                                ks * 16 + (g >> 1) * 8]));

    // ---- Phase A: scores(raw) = Q K^T -> half smem ----
    #pragma unroll 1
    for (int kt = 0; kt < 8; kt++) {
        CPA_WAIT(0);
        __syncthreads();                       // buf kt ready; buf (kt+1)&1 reads done
        if (kt < 7) issue(Kg + (size_t)(kt + 1) * 128 * DH, (kt + 1) & 1);
        const __half* Kt = KV + (kt & 1) * 128 * TS;

        float c[2][4];
        #pragma unroll
        for (int t = 0; t < 2; t++)
            #pragma unroll
            for (int q = 0; q < 4; q++) c[t][q] = 0.f;

        #pragma unroll
        for (int ks = 0; ks < 4; ks++) {
            unsigned bb[4];
            ldm_x4(bb, sptr(&Kt[(wn * 16 + rr + (g >> 1) * 8) * TS +
                                ks * 16 + (g & 1) * 8]));
            mma_f16(c[0], qa[ks], bb[0], bb[1]);
            mma_f16(c[1], qa[ks], bb[2], bb[3]);
        }
        int r = warpM * 16 + (lane >> 2);
        #pragma unroll
        for (int t = 0; t < 2; t++) {
            int cN = kt * 128 + wn * 16 + t * 8 + (lane & 3) * 2;
            *(__half2*)&psh[r * PSH + cN]       = __floats2half2_rn(c[t][0], c[t][1]);
            *(__half2*)&psh[(r + 8) * PSH + cN] = __floats2half2_rn(c[t][2], c[t][3]);
        }
    }
    __syncthreads();   // psh complete; K buffers free

    issue(Vg, 0);      // overlap V tile 0 with softmax

    // ---- softmax: warp owns rows 2w, 2w+1; two smem sweeps, no reg cache ----
    #pragma unroll
    for (int ri = 0; ri < 2; ri++) {
        int r = warp * 2 + ri;
        const int4* mrow4 = (const int4*)(mask + ((size_t)b * Sq + s0 + r) * Sq);
        float sum = 0.f;
        #pragma unroll
        for (int t = 0; t < 8; t++) {
            int j = t * 128 + lane * 4;
            int4 m = mrow4[t * 32 + lane];
            uint2 pp = *(uint2*)&psh[r * PSH + j];
            __half2 p01 = *(__half2*)&pp.x, p23 = *(__half2*)&pp.y;
            float e0 = m.x ? ex2f(__low2float(p01)  * SCL) : 0.f;
            float e1 = m.y ? ex2f(__high2float(p01) * SCL) : 0.f;
            float e2 = m.z ? ex2f(__low2float(p23)  * SCL) : 0.f;
            float e3 = m.w ? ex2f(__high2float(p23) * SCL) : 0.f;
            sum += (e0 + e1) + (e2 + e3);
            __half2 h0 = __floats2half2_rn(e0, e1);
            __half2 h1 = __floats2half2_rn(e2, e3);
            uint2 st; st.x = *(unsigned*)&h0; st.y = *(unsigned*)&h1;
            *(uint2*)&psh[r * PSH + j] = st;
        }
        #pragma unroll
        for (int o = 16; o; o >>= 1) sum += __shfl_xor_sync(~0u, sum, o);
        float inv = 1.0f / sum;
        float4* Ar4 = (float4*)(Aout + (((size_t)h * Bq + b) * Sq + s0 + r) * Sq);
        #pragma unroll
        for (int t = 0; t < 8; t++) {
            int j = t * 128 + lane * 4;
            uint2 pp = *(uint2*)&psh[r * PSH + j];
            __half2 p01 = *(__half2*)&pp.x, p23 = *(__half2*)&pp.y;
            float a0 = __low2float(p01) * inv, a1 = __high2float(p01) * inv;
            float a2 = __low2float(p23) * inv, a3 = __high2float(p23) * inv;
            __stcs(&Ar4[t * 32 + lane], make_float4(a0, a1, a2, a3));
            __half2 h0 = __floats2half2_rn(a0, a1);
            __half2 h1 = __floats2half2_rn(a2, a3);
            uint2 st; st.x = *(unsigned*)&h0; st.y = *(unsigned*)&h1;
            *(uint2*)&psh[r * PSH + j] = st;
        }
    }
    __syncthreads();   // P complete (cross-warp reads in phase B)

    // ---- Phase B: heads(32x64) = P @ V; warp = 16 rows x 8 cols ----
    float o[4];
    o[0] = o[1] = o[2] = o[3] = 0.f;
    const int n0 = wn * 8;

    #pragma unroll 1
    for (int kt = 0; kt < 8; kt++) {
        CPA_WAIT(0);
        __syncthreads();
        if (kt < 7) issue(Vg + (size_t)(kt + 1) * 128 * DH, (kt + 1) & 1);
        const __half* Vt = KV + (kt & 1) * 128 * TS;

        #pragma unroll
        for (int k0 = 0; k0 < 128; k0 += 16) {
            unsigned a[4];
            ldm_x4(a, sptr(&psh[(warpM * 16 + rr + (g & 1) * 8) * PSH +
                                kt * 128 + k0 + (g >> 1) * 8]));
            unsigned bb[2];
            ldm_x2_t(bb, sptr(&Vt[(k0 + (lane & 15)) * TS + n0]));
            mma_f16(o, a, bb[0], bb[1]);
        }
    }

    {
        int r = warpM * 16 + (lane >> 2);
        size_t base = ((size_t)(b * Sq + s0 + r)) * Dm + h * DH;
        int cN = n0 + (lane & 3) * 2;
        *(__half2*)&g_heads[base + cN]          = __floats2half2_rn(o[0], o[1]);
        *(__half2*)&g_heads[base + 8 * Dm + cN] = __floats2half2_rn(o[2], o[3]);
    }
}

// ============================================================================
// K3: out = heads @ Woh^T + bo. fp16 mma, tile 128x128, cp.async 2-stage.
// grid (64, 8), 256 thr.
// ============================================================================
__global__ void __launch_bounds__(256) out_kernel(
    const float* __restrict__ bo, float* __restrict__ out)
{
    extern __shared__ __half hsm[];
    __half* As = hsm;                  // 2 x 128 x 72
    __half* Bs = hsm + 2 * 128 * TS;   // 2 x 128 x 72

    const int tid = threadIdx.x, lane = tid & 31, warp = tid >> 5;
    const int g = lane >> 3, rr = lane & 7;
    const int warpM = warp >> 2;
    const int warpN = warp & 3;
    const int r0 = blockIdx.x * 128, n0 = blockIdx.y * 128;

    auto issue = [&](int kt, int buf) {
        __half* ad = As + buf * 128 * TS;
        __half* bd = Bs + buf * 128 * TS;
        const __half* as = g_heads + (size_t)r0 * Dm + kt * 64;
        const __half* bs = g_Woh   + (size_t)n0 * Dm + kt * 64;
        for (int i = tid; i < 128 * 8; i += 256) {
            int r = i >> 3, q = i & 7;
            cpa16(sptr(&ad[r * TS + q * 8]), as + (size_t)r * Dm + q * 8);
        }
        for (int i = tid; i < 128 * 8; i += 256) {
            int r = i >> 3, q = i & 7;
            cpa16(sptr(&bd[r * TS + q * 8]), bs + (size_t)r * Dm + q * 8);
        }
        CPA_COMMIT();
    };

    float c[4][4][4];
    #pragma unroll
    for (int mi = 0; mi < 4; mi++)
        #pragma unroll
        for (int nt = 0; nt < 4; nt++)
            #pragma unroll
            for (int q = 0; q < 4; q++) c[mi][nt][q] = 0.f;

    issue(0, 0);

    for (int kt = 0; kt < 16; kt++) {
        if (kt < 15) { issue(kt + 1, (kt + 1) & 1); CPA_WAIT(1); }
        else         { CPA_WAIT(0); }
        __syncthreads();
        const __half* At = As + (kt & 1) * 128 * TS;
        const __half* Bt = Bs + (kt & 1) * 128 * TS;

        #pragma unroll
        for (int ks = 0; ks < 4; ks++) {
            int k0 = ks * 16;
            unsigned a[4][4];
            #pragma unroll
            for (int mi = 0; mi < 4; mi++) {
                int row = warpM * 64 + mi * 16 + rr + (g & 1) * 8;
                int col = k0 + (g >> 1) * 8;
                ldm_x4(a[mi], sptr(&At[row * TS + col]));
            }
            unsigned bb[2][4];
            #pragma unroll
            for (int hn = 0; hn < 2; hn++) {
                int row = warpN * 32 + hn * 16 + rr + (g >> 1) * 8;
                int col = k0 + (g & 1) * 8;
                ldm_x4(bb[hn], sptr(&Bt[row * TS + col]));
            }
            #pragma unroll
            for (int mi = 0; mi < 4; mi++) {
                mma_f16(c[mi][0], a[mi], bb[0][0], bb[0][1]);
                mma_f16(c[mi][1], a[mi], bb[0][2], bb[0][3]);
                mma_f16(c[mi][2], a[mi], bb[1][0], bb[1][1]);
                mma_f16(c[mi][3], a[mi], bb[1][2], bb[1][3]);
            }
        }
        __syncthreads();
    }

    #pragma unroll
    for (int mi = 0; mi < 4; mi++) {
        #pragma unroll
        for (int nt = 0; nt < 4; nt++) {
            int r  = r0 + warpM * 64 + mi * 16 + (lane >> 2);
            int cN = n0 + warpN * 32 + nt * 8 + (lane & 3) * 2;
            float b0v = bo[cN], b1v = bo[cN + 1];
            out[(size_t)r * Dm + cN]           = c[mi][nt][0] + b0v;
            out[(size_t)r * Dm + cN + 1]       = c[mi][nt][1] + b1v;
            out[(size_t)(r + 8) * Dm + cN]     = c[mi][nt][2] + b0v;
            out[(size_t)(r + 8) * Dm + cN + 1] = c[mi][nt][3] + b1v;
        }
    }
}

// ============================================================================
extern "C" void kernel_launch(void* const* d_in, const int* in_sizes, int n_in,
                              void* d_out, int out_size)
{
    const float* H    = (const float*)d_in[0];
    const int*   mask = (const int*)  d_in[1];
    const float* Wq   = (const float*)d_in[2];
    const float* bq   = (const float*)d_in[3];
    const float* Wk   = (const float*)d_in[4];
    const float* bk   = (const float*)d_in[5];
    const float* Wv   = (const float*)d_in[6];
    const float* bv   = (const float*)d_in[7];
    const float* Wo   = (const float*)d_in[8];
    const float* bo   = (const float*)d_in[9];

    float* out  = (float*)d_out;
    float* Aout = out + (size_t)Bq * Sq * Dm;

    const int smem1 = (128 * TS + 3 * 64 * TS) * sizeof(__half);              // 46080
    const int smem2 = (32 * PSH + 32 * TS + 2 * 128 * TS) * sizeof(__half);   // 107520
    const int smem3 = 4 * 128 * TS * sizeof(__half);                          // 73728

    cudaFuncSetAttribute(qkv_kernel,  cudaFuncAttributeMaxDynamicSharedMemorySize, smem1);
    cudaFuncSetAttribute(attn_kernel, cudaFuncAttributeMaxDynamicSharedMemorySize, smem2);
    cudaFuncSetAttribute(out_kernel,  cudaFuncAttributeMaxDynamicSharedMemorySize, smem3);

    wconv_kernel<<<1024, 256>>>(Wo);
    hconv_kernel<<<8192, 256>>>(H);
    qkv_kernel<<<dim3(64, NH), 256, smem1>>>(Wq, bq, Wk, bk, Wv, bv);
    attn_kernel<<<dim3(NH, 32, Bq), 512, smem2>>>(mask, Aout);
    out_kernel<<<dim3(64, 8), 256, smem3>>>(bo, out);
}

// round 8
// speedup vs baseline: 1.1767x; 1.0008x over previous
#include <cuda_runtime.h>
#include <cuda_fp16.h>

#define Bq 8
#define Sq 1024
#define Dm 1024
#define NH 16
#define DH 64

#define PSH 1032   // half score/P row stride (2064B: +4 banks/row, LDSM conflict-free)
#define TS  72     // half tile row stride (144B: +4 banks/row)
#define SCL 0.18033688011112043f  // 0.125 * log2(e)

// ---- scratch (device globals: allocation-free rule) ----
__device__ __half g_Hh[(size_t)Bq*Sq*Dm];
__device__ __half g_Q[(size_t)Bq*NH*Sq*DH];
__device__ __half g_K[(size_t)Bq*NH*Sq*DH];
__device__ __half g_V[(size_t)Bq*NH*Sq*DH];
__device__ __half g_heads[(size_t)Bq*Sq*Dm];
__device__ __half g_Woh[(size_t)Dm*Dm];
__device__ unsigned g_mb[(size_t)Bq*Sq*32];   // bit-packed mask

// ---- helpers ----
__device__ __forceinline__ void mma_f16(float c[4], const unsigned a[4],
                                        unsigned b0, unsigned b1) {
    asm volatile(
        "mma.sync.aligned.m16n8k16.row.col.f32.f16.f16.f32 "
        "{%0,%1,%2,%3}, {%4,%5,%6,%7}, {%8,%9}, {%0,%1,%2,%3};"
        : "+f"(c[0]), "+f"(c[1]), "+f"(c[2]), "+f"(c[3])
        : "r"(a[0]), "r"(a[1]), "r"(a[2]), "r"(a[3]), "r"(b0), "r"(b1));
}
__device__ __forceinline__ unsigned sptr(const void* p) {
    return (unsigned)__cvta_generic_to_shared(p);
}
__device__ __forceinline__ void ldm_x4(unsigned r[4], unsigned addr) {
    asm volatile("ldmatrix.sync.aligned.m8n8.x4.shared.b16 {%0,%1,%2,%3}, [%4];"
                 : "=r"(r[0]), "=r"(r[1]), "=r"(r[2]), "=r"(r[3]) : "r"(addr));
}
__device__ __forceinline__ void ldm_x4_t(unsigned r[4], unsigned addr) {
    asm volatile("ldmatrix.sync.aligned.m8n8.x4.trans.shared.b16 {%0,%1,%2,%3}, [%4];"
                 : "=r"(r[0]), "=r"(r[1]), "=r"(r[2]), "=r"(r[3]) : "r"(addr));
}
__device__ __forceinline__ void cpa16(unsigned dst, const void* src) {
    asm volatile("cp.async.cg.shared.global [%0], [%1], 16;" :: "r"(dst), "l"(src));
}
#define CPA_COMMIT() asm volatile("cp.async.commit_group;")
#define CPA_WAIT(n)  asm volatile("cp.async.wait_group %0;" :: "n"(n))
__device__ __forceinline__ float ex2f(float x) {
    float y;
    asm("ex2.approx.f32 %0, %1;" : "=f"(y) : "f"(x));
    return y;
}

// ============================================================================
// K0a: Wo f32 -> half.  K0b: H f32 -> half.  K0c: mask -> bitpack.
// ============================================================================
__global__ void wconv_kernel(const float* __restrict__ Wo) {
    int i = (blockIdx.x * 256 + threadIdx.x) * 4;
    float4 v = *(const float4*)&Wo[i];
    __half2* dst = (__half2*)&g_Woh[i];
    dst[0] = __floats2half2_rn(v.x, v.y);
    dst[1] = __floats2half2_rn(v.z, v.w);
}
__global__ void hconv_kernel(const float* __restrict__ H) {
    int i = (blockIdx.x * 256 + threadIdx.x) * 4;
    float4 v = *(const float4*)&H[i];
    __half2* dst = (__half2*)&g_Hh[i];
    dst[0] = __floats2half2_rn(v.x, v.y);
    dst[1] = __floats2half2_rn(v.z, v.w);
}
__global__ void mpack_kernel(const int* __restrict__ mask) {
    const size_t nwarps = (size_t)gridDim.x * (blockDim.x >> 5);
    size_t wid = ((size_t)blockIdx.x * blockDim.x + threadIdx.x) >> 5;
    int lane = threadIdx.x & 31;
    for (size_t w = wid; w < (size_t)Bq * Sq * 32; w += nwarps) {
        int v = mask[w * 32 + lane];
        unsigned bits = __ballot_sync(~0u, v != 0);
        if (lane == 0) g_mb[w] = bits;
    }
}

// ============================================================================
// K1: fused QKV projection, fp16 mma + ldmatrix. grid (64, NH), 256 thr.
// ============================================================================
__global__ void __launch_bounds__(256) qkv_kernel(
    const float* __restrict__ Wq, const float* __restrict__ bq,
    const float* __restrict__ Wk, const float* __restrict__ bk,
    const float* __restrict__ Wv, const float* __restrict__ bv)
{
    extern __shared__ __half hsm[];
    __half* Hs = hsm;               // 128 x 72
    __half* Ws = hsm + 128 * TS;    // 3 x 64 x 72

    const int tid  = threadIdx.x;
    const int lane = tid & 31;
    const int warp = tid >> 5;
    const int g = lane >> 3, rr = lane & 7;
    const int warpM = warp >> 1;
    const int warpN = warp & 1;
    const int h    = blockIdx.y;
    const int row0 = blockIdx.x * 128;
    const int b    = row0 >> 10;
    const int s    = row0 & 1023;

    for (int i = tid; i < 128 * 8; i += 256) {
        int r = i >> 3, q = i & 7;
        cpa16(sptr(&Hs[r * TS + q * 8]),
              g_Hh + (size_t)(row0 + r) * Dm + h * DH + q * 8);
    }
    CPA_COMMIT();

    const float* Wt[3] = {Wq, Wk, Wv};
    for (int wsel = 0; wsel < 3; wsel++) {
        const float* W = Wt[wsel] + h * DH * DH;
        __half* Wd = Ws + wsel * 64 * TS;
        for (int i = tid; i < 64 * 16; i += 256) {
            int r = i >> 4, q = i & 15;
            float4 v = *(const float4*)&W[r * DH + q * 4];
            __half2* dst = (__half2*)&Wd[r * TS + q * 4];
            dst[0] = __floats2half2_rn(v.x, v.y);
            dst[1] = __floats2half2_rn(v.z, v.w);
        }
    }
    CPA_WAIT(0);
    __syncthreads();

    unsigned a[4][2][4];
    #pragma unroll
    for (int ks = 0; ks < 4; ks++)
        #pragma unroll
        for (int mi = 0; mi < 2; mi++) {
            int row = warpM * 32 + mi * 16 + rr + (g & 1) * 8;
            int col = ks * 16 + (g >> 1) * 8;
            ldm_x4(a[ks][mi], sptr(&Hs[row * TS + col]));
        }

    const float* bt[3] = {bq, bk, bv};
    __half*      Ot[3] = {g_Q, g_K, g_V};

    #pragma unroll
    for (int wsel = 0; wsel < 3; wsel++) {
        const __half* Wd = Ws + wsel * 64 * TS;
        float c[2][4][4];
        #pragma unroll
        for (int mi = 0; mi < 2; mi++)
            #pragma unroll
            for (int t = 0; t < 4; t++)
                #pragma unroll
                for (int q = 0; q < 4; q++) c[mi][t][q] = 0.f;

        #pragma unroll
        for (int ks = 0; ks < 4; ks++) {
            #pragma unroll
            for (int hn = 0; hn < 2; hn++) {
                int row = warpN * 32 + hn * 16 + rr + (g >> 1) * 8;
                int col = ks * 16 + (g & 1) * 8;
                unsigned bb[4];
                ldm_x4(bb, sptr(&Wd[row * TS + col]));
                #pragma unroll
                for (int mi = 0; mi < 2; mi++) {
                    mma_f16(c[mi][hn * 2 + 0], a[ks][mi], bb[0], bb[1]);
                    mma_f16(c[mi][hn * 2 + 1], a[ks][mi], bb[2], bb[3]);
                }
            }
        }

        const float* bias = bt[wsel] + h * DH;
        __half* O = Ot[wsel] + ((size_t)(b * NH + h) * Sq + s) * DH;
        #pragma unroll
        for (int mi = 0; mi < 2; mi++)
            #pragma unroll
            for (int t = 0; t < 4; t++) {
                int r  = warpM * 32 + mi * 16 + (lane >> 2);
                int cN = warpN * 32 + t * 8 + (lane & 3) * 2;
                float b0v = bias[cN], b1v = bias[cN + 1];
                *(__half2*)&O[(size_t)r * DH + cN] =
                    __floats2half2_rn(c[mi][t][0] + b0v, c[mi][t][1] + b1v);
                *(__half2*)&O[(size_t)(r + 8) * DH + cN] =
                    __floats2half2_rn(c[mi][t][2] + b0v, c[mi][t][3] + b1v);
            }
    }
}

// ============================================================================
// K2: attention (R3 structure + bitmask fused-exp + rinv defer).
// 32 query rows, 256 thr / 8 warps. psh holds EXP values (unnormalized).
// Phase A epilogue: mask bits + ex2 + Z partials. A-sweep: LDS*inv -> STG.
// Phase B: unnorm P @ V, scale by rinv in epilogue. grid (NH, 32, Bq).
// ============================================================================
__global__ void __launch_bounds__(256) attn_kernel(float* __restrict__ Aout)
{
    extern __shared__ __half hsm[];
    __half*   psh  = hsm;                         // 32 x 1032: exp -> P
    __half*   Qs   = psh + 32 * PSH;              // 32 x 72
    __half*   KV   = Qs + 32 * TS;                // 2 x 128 x 72
    unsigned* mb   = (unsigned*)(KV + 2 * 128 * TS);  // 32 x 32 words
    float*    zred = (float*)(mb + 32 * 32);      // 32 x 4
    float*    rinv = zred + 32 * 4;               // 32

    const int tid = threadIdx.x, lane = tid & 31, warp = tid >> 5;
    const int h = blockIdx.x, b = blockIdx.z, s0 = blockIdx.y * 32;
    const int g = lane >> 3, rr = lane & 7;
    const int warpM = warp >> 2;   // 0..1: 16 rows
    const int warpN = warp & 3;    // 0..3: 32 keys (A) / 16 head-cols (B)

    const __half* Qg = g_Q + ((size_t)(b * NH + h) * Sq + s0) * DH;
    const __half* Kg = g_K + (size_t)(b * NH + h) * Sq * DH;
    const __half* Vg = g_V + (size_t)(b * NH + h) * Sq * DH;

    auto issue = [&](const __half* src, int buf) {
        __half* dst = KV + buf * 128 * TS;
        for (int i = tid; i < 128 * 8; i += 256) {
            int r = i >> 3, q = i & 7;
            cpa16(sptr(&dst[r * TS + q * 8]), src + (size_t)r * DH + q * 8);
        }
        CPA_COMMIT();
    };

    issue(Kg, 0);
    // Q tile 32x64 + mask bits 32x32 words
    for (int i = tid; i < 32 * 8; i += 256) {
        int r = i >> 3, q = i & 7;
        *(uint4*)&Qs[r * TS + q * 8] = ((const uint4*)Qg)[r * 8 + q];
    }
    {
        const unsigned* src = g_mb + ((size_t)b * Sq + s0) * 32;
        for (int i = tid; i < 1024; i += 256) mb[i] = src[i];
    }
    __syncthreads();

    // Q fragments (loop-invariant)
    unsigned qa[4][4];
    #pragma unroll
    for (int ks = 0; ks < 4; ks++)
        ldm_x4(qa[ks], sptr(&Qs[(warpM * 16 + rr + (g & 1) * 8) * TS +
                                ks * 16 + (g >> 1) * 8]));

    const int r = warpM * 16 + (lane >> 2);
    const int jb = (lane & 3) * 2;
    float z0 = 0.f, z1 = 0.f;

    // ---- Phase A: exp(Q K^T * scl) -> psh, Z partials in regs ----
    #pragma unroll 1
    for (int kt = 0; kt < 8; kt++) {
        CPA_WAIT(0);
        __syncthreads();
        if (kt < 7) issue(Kg + (size_t)(kt + 1) * 128 * DH, (kt + 1) & 1);
        const __half* Kt = KV + (kt & 1) * 128 * TS;

        float c[4][4];
        #pragma unroll
        for (int t = 0; t < 4; t++)
            #pragma unroll
            for (int q = 0; q < 4; q++) c[t][q] = 0.f;

        #pragma unroll
        for (int ks = 0; ks < 4; ks++) {
            #pragma unroll
            for (int hn = 0; hn < 2; hn++) {
                unsigned bb[4];
                ldm_x4(bb, sptr(&Kt[(warpN * 32 + hn * 16 + rr + (g >> 1) * 8) * TS +
                                    ks * 16 + (g & 1) * 8]));
                mma_f16(c[hn * 2 + 0], qa[ks], bb[0], bb[1]);
                mma_f16(c[hn * 2 + 1], qa[ks], bb[2], bb[3]);
            }
        }

        unsigned w0 = mb[r * 32 + kt * 4 + warpN];
        unsigned w1 = mb[(r + 8) * 32 + kt * 4 + warpN];
        #pragma unroll
        for (int t = 0; t < 4; t++) {
            int j = t * 8 + jb;
            float e00 = (w0 >> j)       & 1 ? ex2f(c[t][0] * SCL) : 0.f;
            float e01 = (w0 >> (j + 1)) & 1 ? ex2f(c[t][1] * SCL) : 0.f;
            float e10 = (w1 >> j)       & 1 ? ex2f(c[t][2] * SCL) : 0.f;
            float e11 = (w1 >> (j + 1)) & 1 ? ex2f(c[t][3] * SCL) : 0.f;
            z0 += e00 + e01;
            z1 += e10 + e11;
            int cN = kt * 128 + warpN * 32 + t * 8 + jb;
            *(__half2*)&psh[r * PSH + cN]       = __floats2half2_rn(e00, e01);
            *(__half2*)&psh[(r + 8) * PSH + cN] = __floats2half2_rn(e10, e11);
        }
    }

    // Z reduce: quad (cols) then cross-warp (warpN) via smem
    z0 += __shfl_xor_sync(~0u, z0, 1); z0 += __shfl_xor_sync(~0u, z0, 2);
    z1 += __shfl_xor_sync(~0u, z1, 1); z1 += __shfl_xor_sync(~0u, z1, 2);
    if ((lane & 3) == 0) {
        zred[r * 4 + warpN]       = z0;
        zred[(r + 8) * 4 + warpN] = z1;
    }
    __syncthreads();   // psh + zred complete; K buffers free

    issue(Vg, 0);      // overlap V tile 0 with rinv + A-sweep

    if (tid < 32)
        rinv[tid] = 1.0f / (zred[tid * 4] + zred[tid * 4 + 1] +
                            zred[tid * 4 + 2] + zred[tid * 4 + 3]);
    __syncthreads();

    // ---- A-sweep: A = e * inv, one LDS pass + streaming STG ----
    #pragma unroll
    for (int ri = 0; ri < 4; ri++) {
        int rw = warp * 4 + ri;
        float inv = rinv[rw];
        float4* Ar4 = (float4*)(Aout + (((size_t)h * Bq + b) * Sq + s0 + rw) * Sq);
        #pragma unroll
        for (int t = 0; t < 8; t++) {
            int j = t * 128 + lane * 4;
            uint2 pp = *(uint2*)&psh[rw * PSH + j];
            __half2 p01 = *(__half2*)&pp.x, p23 = *(__half2*)&pp.y;
            __stcs(&Ar4[t * 32 + lane],
                   make_float4(__low2float(p01) * inv, __high2float(p01) * inv,
                               __low2float(p23) * inv, __high2float(p23) * inv));
        }
    }

    // ---- Phase B: heads = (unnorm P) @ V, scaled by rinv at the end ----
    float c2[2][4];
    #pragma unroll
    for (int t = 0; t < 2; t++)
        #pragma unroll
        for (int q = 0; q < 4; q++) c2[t][q] = 0.f;

    const int n0 = warpN * 16;
    #pragma unroll 1
    for (int kt = 0; kt < 8; kt++) {
        CPA_WAIT(0);
        __syncthreads();
        if (kt < 7) issue(Vg + (size_t)(kt + 1) * 128 * DH, (kt + 1) & 1);
        const __half* Vt = KV + (kt & 1) * 128 * TS;

        #pragma unroll
        for (int k0 = 0; k0 < 128; k0 += 16) {
            unsigned a[4];
            ldm_x4(a, sptr(&psh[(warpM * 16 + rr + (g & 1) * 8) * PSH +
                                kt * 128 + k0 + (g >> 1) * 8]));
            unsigned bb[4];
            ldm_x4_t(bb, sptr(&Vt[(k0 + rr + (g & 1) * 8) * TS + n0 + (g >> 1) * 8]));
            mma_f16(c2[0], a, bb[0], bb[1]);
            mma_f16(c2[1], a, bb[2], bb[3]);
        }
    }

    {
        float i0 = rinv[r], i1 = rinv[r + 8];
        size_t base = ((size_t)(b * Sq + s0 + r)) * Dm + h * DH;
        #pragma unroll
        for (int t = 0; t < 2; t++) {
            int cN = n0 + t * 8 + jb;
            *(__half2*)&g_heads[base + cN] =
                __floats2half2_rn(c2[t][0] * i0, c2[t][1] * i0);
            *(__half2*)&g_heads[base + 8 * Dm + cN] =
                __floats2half2_rn(c2[t][2] * i1, c2[t][3] * i1);
        }
    }
}

// ============================================================================
// K3: out = heads @ Woh^T + bo. fp16 mma, tile 128x128, cp.async 2-stage.
// grid (64, 8), 256 thr.
// ============================================================================
__global__ void __launch_bounds__(256) out_kernel(
    const float* __restrict__ bo, float* __restrict__ out)
{
    extern __shared__ __half hsm[];
    __half* As = hsm;                  // 2 x 128 x 72
    __half* Bs = hsm + 2 * 128 * TS;   // 2 x 128 x 72

    const int tid = threadIdx.x, lane = tid & 31, warp = tid >> 5;
    const int g = lane >> 3, rr = lane & 7;
    const int warpM = warp >> 2;
    const int warpN = warp & 3;
    const int r0 = blockIdx.x * 128, n0 = blockIdx.y * 128;

    auto issue = [&](int kt, int buf) {
        __half* ad = As + buf * 128 * TS;
        __half* bd = Bs + buf * 128 * TS;
        const __half* as = g_heads + (size_t)r0 * Dm + kt * 64;
        const __half* bs = g_Woh   + (size_t)n0 * Dm + kt * 64;
        for (int i = tid; i < 128 * 8; i += 256) {
            int r = i >> 3, q = i & 7;
            cpa16(sptr(&ad[r * TS + q * 8]), as + (size_t)r * Dm + q * 8);
        }
        for (int i = tid; i < 128 * 8; i += 256) {
            int r = i >> 3, q = i & 7;
            cpa16(sptr(&bd[r * TS + q * 8]), bs + (size_t)r * Dm + q * 8);
        }
        CPA_COMMIT();
    };

    float c[4][4][4];
    #pragma unroll
    for (int mi = 0; mi < 4; mi++)
        #pragma unroll
        for (int nt = 0; nt < 4; nt++)
            #pragma unroll
            for (int q = 0; q < 4; q++) c[mi][nt][q] = 0.f;

    issue(0, 0);

    for (int kt = 0; kt < 16; kt++) {
        if (kt < 15) { issue(kt + 1, (kt + 1) & 1); CPA_WAIT(1); }
        else         { CPA_WAIT(0); }
        __syncthreads();
        const __half* At = As + (kt & 1) * 128 * TS;
        const __half* Bt = Bs + (kt & 1) * 128 * TS;

        #pragma unroll
        for (int ks = 0; ks < 4; ks++) {
            int k0 = ks * 16;
            unsigned a[4][4];
            #pragma unroll
            for (int mi = 0; mi < 4; mi++) {
                int row = warpM * 64 + mi * 16 + rr + (g & 1) * 8;
                int col = k0 + (g >> 1) * 8;
                ldm_x4(a[mi], sptr(&At[row * TS + col]));
            }
            unsigned bb[2][4];
            #pragma unroll
            for (int hn = 0; hn < 2; hn++) {
                int row = warpN * 32 + hn * 16 + rr + (g >> 1) * 8;
                int col = k0 + (g & 1) * 8;
                ldm_x4(bb[hn], sptr(&Bt[row * TS + col]));
            }
            #pragma unroll
            for (int mi = 0; mi < 4; mi++) {
                mma_f16(c[mi][0], a[mi], bb[0][0], bb[0][1]);
                mma_f16(c[mi][1], a[mi], bb[0][2], bb[0][3]);
                mma_f16(c[mi][2], a[mi], bb[1][0], bb[1][1]);
                mma_f16(c[mi][3], a[mi], bb[1][2], bb[1][3]);
            }
        }
        __syncthreads();
    }

    #pragma unroll
    for (int mi = 0; mi < 4; mi++) {
        #pragma unroll
        for (int nt = 0; nt < 4; nt++) {
            int r  = r0 + warpM * 64 + mi * 16 + (lane >> 2);
            int cN = n0 + warpN * 32 + nt * 8 + (lane & 3) * 2;
            float b0v = bo[cN], b1v = bo[cN + 1];
            out[(size_t)r * Dm + cN]           = c[mi][nt][0] + b0v;
            out[(size_t)r * Dm + cN + 1]       = c[mi][nt][1] + b1v;
            out[(size_t)(r + 8) * Dm + cN]     = c[mi][nt][2] + b0v;
            out[(size_t)(r + 8) * Dm + cN + 1] = c[mi][nt][3] + b1v;
        }
    }
}

// ============================================================================
extern "C" void kernel_launch(void* const* d_in, const int* in_sizes, int n_in,
                              void* d_out, int out_size)
{
    const float* H    = (const float*)d_in[0];
    const int*   mask = (const int*)  d_in[1];
    const float* Wq   = (const float*)d_in[2];
    const float* bq   = (const float*)d_in[3];
    const float* Wk   = (const float*)d_in[4];
    const float* bk   = (const float*)d_in[5];
    const float* Wv   = (const float*)d_in[6];
    const float* bv   = (const float*)d_in[7];
    const float* Wo   = (const float*)d_in[8];
    const float* bo   = (const float*)d_in[9];

    float* out  = (float*)d_out;
    float* Aout = out + (size_t)Bq * Sq * Dm;

    const int smem1 = (128 * TS + 3 * 64 * TS) * sizeof(__half);            // 46080
    const int smem2 = (32 * PSH + 32 * TS + 2 * 128 * TS) * sizeof(__half)
                    + 32 * 32 * 4 + 32 * 4 * 4 + 32 * 4;                    // 112256
    const int smem3 = 4 * 128 * TS * sizeof(__half);                        // 73728

    cudaFuncSetAttribute(qkv_kernel,  cudaFuncAttributeMaxDynamicSharedMemorySize, smem1);
    cudaFuncSetAttribute(attn_kernel, cudaFuncAttributeMaxDynamicSharedMemorySize, smem2);
    cudaFuncSetAttribute(out_kernel,  cudaFuncAttributeMaxDynamicSharedMemorySize, smem3);

    wconv_kernel<<<1024, 256>>>(Wo);
    hconv_kernel<<<8192, 256>>>(H);
    mpack_kernel<<<512, 256>>>(mask);
    qkv_kernel<<<dim3(64, NH), 256, smem1>>>(Wq, bq, Wk, bk, Wv, bv);
    attn_kernel<<<dim3(NH, 32, Bq), 256, smem2>>>(Aout);
    out_kernel<<<dim3(64, 8), 256, smem3>>>(bo, out);
}

// round 9
// speedup vs baseline: 1.1810x; 1.0036x over previous
#include <cuda_runtime.h>
#include <cuda_fp16.h>

#define Bq 8
#define Sq 1024
#define Dm 1024
#define NH 16
#define DH 64

#define PSH 1032   // half score/P row stride (2064B: +4 banks/row, LDSM conflict-free)
#define TS  72     // half tile row stride (144B: +4 banks/row)
#define SCL 0.18033688011112043f  // 0.125 * log2(e)

// ---- scratch (device globals: allocation-free rule) ----
__device__ __half g_Hh[(size_t)Bq*Sq*Dm];
__device__ __half g_Q[(size_t)Bq*NH*Sq*DH];
__device__ __half g_K[(size_t)Bq*NH*Sq*DH];
__device__ __half g_V[(size_t)Bq*NH*Sq*DH];
__device__ __half g_heads[(size_t)Bq*Sq*Dm];
__device__ __half g_Woh[(size_t)Dm*Dm];
__device__ unsigned g_mb[(size_t)Bq*Sq*32];   // bit-packed mask

// ---- helpers ----
__device__ __forceinline__ void mma_f16(float c[4], const unsigned a[4],
                                        unsigned b0, unsigned b1) {
    asm volatile(
        "mma.sync.aligned.m16n8k16.row.col.f32.f16.f16.f32 "
        "{%0,%1,%2,%3}, {%4,%5,%6,%7}, {%8,%9}, {%0,%1,%2,%3};"
        : "+f"(c[0]), "+f"(c[1]), "+f"(c[2]), "+f"(c[3])
        : "r"(a[0]), "r"(a[1]), "r"(a[2]), "r"(a[3]), "r"(b0), "r"(b1));
}
__device__ __forceinline__ unsigned sptr(const void* p) {
    return (unsigned)__cvta_generic_to_shared(p);
}
__device__ __forceinline__ void ldm_x4(unsigned r[4], unsigned addr) {
    asm volatile("ldmatrix.sync.aligned.m8n8.x4.shared.b16 {%0,%1,%2,%3}, [%4];"
                 : "=r"(r[0]), "=r"(r[1]), "=r"(r[2]), "=r"(r[3]) : "r"(addr));
}
__device__ __forceinline__ void ldm_x4_t(unsigned r[4], unsigned addr) {
    asm volatile("ldmatrix.sync.aligned.m8n8.x4.trans.shared.b16 {%0,%1,%2,%3}, [%4];"
                 : "=r"(r[0]), "=r"(r[1]), "=r"(r[2]), "=r"(r[3]) : "r"(addr));
}
__device__ __forceinline__ void cpa16(unsigned dst, const void* src) {
    asm volatile("cp.async.cg.shared.global [%0], [%1], 16;" :: "r"(dst), "l"(src));
}
#define CPA_COMMIT() asm volatile("cp.async.commit_group;")
#define CPA_WAIT(n)  asm volatile("cp.async.wait_group %0;" :: "n"(n))
__device__ __forceinline__ float ex2f(float x) {
    float y;
    asm("ex2.approx.f32 %0, %1;" : "=f"(y) : "f"(x));
    return y;
}

// ============================================================================
// K0a: Wo f32 -> half.  K0b: H f32 -> half.  K0c: mask -> bitpack.
// ============================================================================
__global__ void wconv_kernel(const float* __restrict__ Wo) {
    int i = (blockIdx.x * 256 + threadIdx.x) * 4;
    float4 v = *(const float4*)&Wo[i];
    __half2* dst = (__half2*)&g_Woh[i];
    dst[0] = __floats2half2_rn(v.x, v.y);
    dst[1] = __floats2half2_rn(v.z, v.w);
}
__global__ void hconv_kernel(const float* __restrict__ H) {
    int i = (blockIdx.x * 256 + threadIdx.x) * 4;
    float4 v = *(const float4*)&H[i];
    __half2* dst = (__half2*)&g_Hh[i];
    dst[0] = __floats2half2_rn(v.x, v.y);
    dst[1] = __floats2half2_rn(v.z, v.w);
}
__global__ void mpack_kernel(const int* __restrict__ mask) {
    const size_t nwarps = (size_t)gridDim.x * (blockDim.x >> 5);
    size_t wid = ((size_t)blockIdx.x * blockDim.x + threadIdx.x) >> 5;
    int lane = threadIdx.x & 31;
    for (size_t w = wid; w < (size_t)Bq * Sq * 32; w += nwarps) {
        int v = mask[w * 32 + lane];
        unsigned bits = __ballot_sync(~0u, v != 0);
        if (lane == 0) g_mb[w] = bits;
    }
}

// ============================================================================
// K1: fused QKV projection, fp16 mma + ldmatrix. grid (64, NH), 256 thr.
// ============================================================================
__global__ void __launch_bounds__(256) qkv_kernel(
    const float* __restrict__ Wq, const float* __restrict__ bq,
    const float* __restrict__ Wk, const float* __restrict__ bk,
    const float* __restrict__ Wv, const float* __restrict__ bv)
{
    extern __shared__ __half hsm[];
    __half* Hs = hsm;               // 128 x 72
    __half* Ws = hsm + 128 * TS;    // 3 x 64 x 72

    const int tid  = threadIdx.x;
    const int lane = tid & 31;
    const int warp = tid >> 5;
    const int g = lane >> 3, rr = lane & 7;
    const int warpM = warp >> 1;
    const int warpN = warp & 1;
    const int h    = blockIdx.y;
    const int row0 = blockIdx.x * 128;
    const int b    = row0 >> 10;
    const int s    = row0 & 1023;

    for (int i = tid; i < 128 * 8; i += 256) {
        int r = i >> 3, q = i & 7;
        cpa16(sptr(&Hs[r * TS + q * 8]),
              g_Hh + (size_t)(row0 + r) * Dm + h * DH + q * 8);
    }
    CPA_COMMIT();

    const float* Wt[3] = {Wq, Wk, Wv};
    for (int wsel = 0; wsel < 3; wsel++) {
        const float* W = Wt[wsel] + h * DH * DH;
        __half* Wd = Ws + wsel * 64 * TS;
        for (int i = tid; i < 64 * 16; i += 256) {
            int r = i >> 4, q = i & 15;
            float4 v = *(const float4*)&W[r * DH + q * 4];
            __half2* dst = (__half2*)&Wd[r * TS + q * 4];
            dst[0] = __floats2half2_rn(v.x, v.y);
            dst[1] = __floats2half2_rn(v.z, v.w);
        }
    }
    CPA_WAIT(0);
    __syncthreads();

    unsigned a[4][2][4];
    #pragma unroll
    for (int ks = 0; ks < 4; ks++)
        #pragma unroll
        for (int mi = 0; mi < 2; mi++) {
            int row = warpM * 32 + mi * 16 + rr + (g & 1) * 8;
            int col = ks * 16 + (g >> 1) * 8;
            ldm_x4(a[ks][mi], sptr(&Hs[row * TS + col]));
        }

    const float* bt[3] = {bq, bk, bv};
    __half*      Ot[3] = {g_Q, g_K, g_V};

    #pragma unroll
    for (int wsel = 0; wsel < 3; wsel++) {
        const __half* Wd = Ws + wsel * 64 * TS;
        float c[2][4][4];
        #pragma unroll
        for (int mi = 0; mi < 2; mi++)
            #pragma unroll
            for (int t = 0; t < 4; t++)
                #pragma unroll
                for (int q = 0; q < 4; q++) c[mi][t][q] = 0.f;

        #pragma unroll
        for (int ks = 0; ks < 4; ks++) {
            #pragma unroll
            for (int hn = 0; hn < 2; hn++) {
                int row = warpN * 32 + hn * 16 + rr + (g >> 1) * 8;
                int col = ks * 16 + (g & 1) * 8;
                unsigned bb[4];
                ldm_x4(bb, sptr(&Wd[row * TS + col]));
                #pragma unroll
                for (int mi = 0; mi < 2; mi++) {
                    mma_f16(c[mi][hn * 2 + 0], a[ks][mi], bb[0], bb[1]);
                    mma_f16(c[mi][hn * 2 + 1], a[ks][mi], bb[2], bb[3]);
                }
            }
        }

        const float* bias = bt[wsel] + h * DH;
        __half* O = Ot[wsel] + ((size_t)(b * NH + h) * Sq + s) * DH;
        #pragma unroll
        for (int mi = 0; mi < 2; mi++)
            #pragma unroll
            for (int t = 0; t < 4; t++) {
                int r  = warpM * 32 + mi * 16 + (lane >> 2);
                int cN = warpN * 32 + t * 8 + (lane & 3) * 2;
                float b0v = bias[cN], b1v = bias[cN + 1];
                *(__half2*)&O[(size_t)r * DH + cN] =
                    __floats2half2_rn(c[mi][t][0] + b0v, c[mi][t][1] + b1v);
                *(__half2*)&O[(size_t)(r + 8) * DH + cN] =
                    __floats2half2_rn(c[mi][t][2] + b0v, c[mi][t][3] + b1v);
            }
    }
}

// ============================================================================
// K2: attention — R3 structure (measured best) + bitmask softmax.
// 32 query rows, 256 thr / 8 warps, 2-stage cp.async, trailing syncs.
// Phase A: raw scores -> psh (half). Softmax: reg cache, mask bits from smem,
// no-max ex2; writes A (f32 stcs) + normalized P (half, in place).
// Phase B: P @ V. grid (NH, 32, Bq) h-fastest.
// ============================================================================
__global__ void __launch_bounds__(256) attn_kernel(float* __restrict__ Aout)
{
    extern __shared__ __half hsm[];
    __half*   psh = hsm;                         // 32 x 1032: scores -> P
    __half*   Qs  = psh + 32 * PSH;              // 32 x 72
    __half*   KV  = Qs + 32 * TS;                // 2 x 128 x 72
    unsigned* mb  = (unsigned*)(KV + 2 * 128 * TS);  // 32 x 32 words

    const int tid = threadIdx.x, lane = tid & 31, warp = tid >> 5;
    const int h = blockIdx.x, b = blockIdx.z, s0 = blockIdx.y * 32;
    const int g = lane >> 3, rr = lane & 7;
    const int warpM = warp >> 2;   // 0..1: 16 rows
    const int warpN = warp & 3;    // 0..3: 32 keys (A) / 16 head-cols (B)

    const __half* Qg = g_Q + ((size_t)(b * NH + h) * Sq + s0) * DH;
    const __half* Kg = g_K + (size_t)(b * NH + h) * Sq * DH;
    const __half* Vg = g_V + (size_t)(b * NH + h) * Sq * DH;

    auto issue = [&](const __half* src, int buf) {
        __half* dst = KV + buf * 128 * TS;
        for (int i = tid; i < 128 * 8; i += 256) {
            int r = i >> 3, q = i & 7;
            cpa16(sptr(&dst[r * TS + q * 8]), src + (size_t)r * DH + q * 8);
        }
        CPA_COMMIT();
    };

    issue(Kg, 0);
    // Q tile 32x64 + mask bits 32x32 words
    for (int i = tid; i < 32 * 8; i += 256) {
        int r = i >> 3, q = i & 7;
        *(uint4*)&Qs[r * TS + q * 8] = ((const uint4*)Qg)[r * 8 + q];
    }
    {
        const unsigned* src = g_mb + ((size_t)b * Sq + s0) * 32;
        for (int i = tid; i < 1024; i += 256) mb[i] = src[i];
    }
    __syncthreads();

    // Q fragments (loop-invariant)
    unsigned qa[4][4];
    #pragma unroll
    for (int ks = 0; ks < 4; ks++)
        ldm_x4(qa[ks], sptr(&Qs[(warpM * 16 + rr + (g & 1) * 8) * TS +
                                ks * 16 + (g >> 1) * 8]));

    // ---- Phase A: raw scores = Q K^T -> half smem ----
    for (int kt = 0; kt < 8; kt++) {
        if (kt < 7) {
            issue(Kg + (size_t)(kt + 1) * 128 * DH, (kt + 1) & 1);
            CPA_WAIT(1);
        } else {
            CPA_WAIT(0);
        }
        __syncthreads();
        const __half* Kt = KV + (kt & 1) * 128 * TS;

        float c[4][4];
        #pragma unroll
        for (int t = 0; t < 4; t++)
            #pragma unroll
            for (int q = 0; q < 4; q++) c[t][q] = 0.f;

        #pragma unroll
        for (int ks = 0; ks < 4; ks++) {
            #pragma unroll
            for (int hn = 0; hn < 2; hn++) {
                unsigned bb[4];
                ldm_x4(bb, sptr(&Kt[(warpN * 32 + hn * 16 + rr + (g >> 1) * 8) * TS +
                                    ks * 16 + (g & 1) * 8]));
                mma_f16(c[hn * 2 + 0], qa[ks], bb[0], bb[1]);
                mma_f16(c[hn * 2 + 1], qa[ks], bb[2], bb[3]);
            }
        }
        int r = warpM * 16 + (lane >> 2);
        #pragma unroll
        for (int t = 0; t < 4; t++) {
            int cN = kt * 128 + warpN * 32 + t * 8 + (lane & 3) * 2;
            *(__half2*)&psh[r * PSH + cN]       = __floats2half2_rn(c[t][0], c[t][1]);
            *(__half2*)&psh[(r + 8) * PSH + cN] = __floats2half2_rn(c[t][2], c[t][3]);
        }
        __syncthreads();
    }

    issue(Vg, 0);      // overlap V tile 0 with softmax (buf0 reads done @ kt=6 sync)

    // ---- softmax: warp owns rows 4w..4w+3; reg cache; bitmask from smem ----
    #pragma unroll
    for (int ri = 0; ri < 4; ri++) {
        int rw = warp * 4 + ri;
        float sv[32];
        float sum = 0.f;
        #pragma unroll
        for (int t = 0; t < 32; t++) {
            int j = t * 32 + lane;
            float s = __half2float(psh[rw * PSH + j]);
            float e = ((mb[rw * 32 + t] >> lane) & 1) ? ex2f(s * SCL) : 0.f;
            sv[t] = e;
            sum += e;
        }
        #pragma unroll
        for (int o = 16; o; o >>= 1) sum += __shfl_xor_sync(~0u, sum, o);
        float inv = 1.0f / sum;
        float* Ar = Aout + (((size_t)h * Bq + b) * Sq + s0 + rw) * Sq;
        #pragma unroll
        for (int t = 0; t < 32; t++) {
            int j = t * 32 + lane;
            float a = sv[t] * inv;
            __stcs(&Ar[j], a);
            psh[rw * PSH + j] = __float2half_rn(a);
        }
    }
    __syncthreads();   // P complete (cross-warp reads in phase B)

    // ---- Phase B: heads(32x64) = P @ V ----
    float c2[2][4];
    #pragma unroll
    for (int t = 0; t < 2; t++)
        #pragma unroll
        for (int q = 0; q < 4; q++) c2[t][q] = 0.f;

    const int n0 = warpN * 16;
    for (int kt = 0; kt < 8; kt++) {
        if (kt < 7) {
            issue(Vg + (size_t)(kt + 1) * 128 * DH, (kt + 1) & 1);
            CPA_WAIT(1);
        } else {
            CPA_WAIT(0);
        }
        __syncthreads();
        const __half* Vt = KV + (kt & 1) * 128 * TS;

        #pragma unroll
        for (int k0 = 0; k0 < 128; k0 += 16) {
            unsigned a[4];
            ldm_x4(a, sptr(&psh[(warpM * 16 + rr + (g & 1) * 8) * PSH +
                                kt * 128 + k0 + (g >> 1) * 8]));
            unsigned bb[4];
            ldm_x4_t(bb, sptr(&Vt[(k0 + rr + (g & 1) * 8) * TS + n0 + (g >> 1) * 8]));
            mma_f16(c2[0], a, bb[0], bb[1]);
            mma_f16(c2[1], a, bb[2], bb[3]);
        }
        __syncthreads();
    }

    {
        int r = warpM * 16 + (lane >> 2);
        size_t base = ((size_t)(b * Sq + s0 + r)) * Dm + h * DH;
        #pragma unroll
        for (int t = 0; t < 2; t++) {
            int cN = n0 + t * 8 + (lane & 3) * 2;
            *(__half2*)&g_heads[base + cN] =
                __floats2half2_rn(c2[t][0], c2[t][1]);
            *(__half2*)&g_heads[base + 8 * Dm + cN] =
                __floats2half2_rn(c2[t][2], c2[t][3]);
        }
    }
}

// ============================================================================
// K3: out = heads @ Woh^T + bo. fp16 mma, tile 128x128, cp.async 2-stage.
// grid (64, 8), 256 thr.
// ============================================================================
__global__ void __launch_bounds__(256) out_kernel(
    const float* __restrict__ bo, float* __restrict__ out)
{
    extern __shared__ __half hsm[];
    __half* As = hsm;                  // 2 x 128 x 72
    __half* Bs = hsm + 2 * 128 * TS;   // 2 x 128 x 72

    const int tid = threadIdx.x, lane = tid & 31, warp = tid >> 5;
    const int g = lane >> 3, rr = lane & 7;
    const int warpM = warp >> 2;
    const int warpN = warp & 3;
    const int r0 = blockIdx.x * 128, n0 = blockIdx.y * 128;

    auto issue = [&](int kt, int buf) {
        __half* ad = As + buf * 128 * TS;
        __half* bd = Bs + buf * 128 * TS;
        const __half* as = g_heads + (size_t)r0 * Dm + kt * 64;
        const __half* bs = g_Woh   + (size_t)n0 * Dm + kt * 64;
        for (int i = tid; i < 128 * 8; i += 256) {
            int r = i >> 3, q = i & 7;
            cpa16(sptr(&ad[r * TS + q * 8]), as + (size_t)r * Dm + q * 8);
        }
        for (int i = tid; i < 128 * 8; i += 256) {
            int r = i >> 3, q = i & 7;
            cpa16(sptr(&bd[r * TS + q * 8]), bs + (size_t)r * Dm + q * 8);
        }
        CPA_COMMIT();
    };

    float c[4][4][4];
    #pragma unroll
    for (int mi = 0; mi < 4; mi++)
        #pragma unroll
        for (int nt = 0; nt < 4; nt++)
            #pragma unroll
            for (int q = 0; q < 4; q++) c[mi][nt][q] = 0.f;

    issue(0, 0);

    for (int kt = 0; kt < 16; kt++) {
        if (kt < 15) { issue(kt + 1, (kt + 1) & 1); CPA_WAIT(1); }
        else         { CPA_WAIT(0); }
        __syncthreads();
        const __half* At = As + (kt & 1) * 128 * TS;
        const __half* Bt = Bs + (kt & 1) * 128 * TS;

        #pragma unroll
        for (int ks = 0; ks < 4; ks++) {
            int k0 = ks * 16;
            unsigned a[4][4];
            #pragma unroll
            for (int mi = 0; mi < 4; mi++) {
                int row = warpM * 64 + mi * 16 + rr + (g & 1) * 8;
                int col = k0 + (g >> 1) * 8;
                ldm_x4(a[mi], sptr(&At[row * TS + col]));
            }
            unsigned bb[2][4];
            #pragma unroll
            for (int hn = 0; hn < 2; hn++) {
                int row = warpN * 32 + hn * 16 + rr + (g >> 1) * 8;
                int col = k0 + (g & 1) * 8;
                ldm_x4(bb[hn], sptr(&Bt[row * TS + col]));
            }
            #pragma unroll
            for (int mi = 0; mi < 4; mi++) {
                mma_f16(c[mi][0], a[mi], bb[0][0], bb[0][1]);
                mma_f16(c[mi][1], a[mi], bb[0][2], bb[0][3]);
                mma_f16(c[mi][2], a[mi], bb[1][0], bb[1][1]);
                mma_f16(c[mi][3], a[mi], bb[1][2], bb[1][3]);
            }
        }
        __syncthreads();
    }

    #pragma unroll
    for (int mi = 0; mi < 4; mi++) {
        #pragma unroll
        for (int nt = 0; nt < 4; nt++) {
            int r  = r0 + warpM * 64 + mi * 16 + (lane >> 2);
            int cN = n0 + warpN * 32 + nt * 8 + (lane & 3) * 2;
            float b0v = bo[cN], b1v = bo[cN + 1];
            out[(size_t)r * Dm + cN]           = c[mi][nt][0] + b0v;
            out[(size_t)r * Dm + cN + 1]       = c[mi][nt][1] + b1v;
            out[(size_t)(r + 8) * Dm + cN]     = c[mi][nt][2] + b0v;
            out[(size_t)(r + 8) * Dm + cN + 1] = c[mi][nt][3] + b1v;
        }
    }
}

// ============================================================================
extern "C" void kernel_launch(void* const* d_in, const int* in_sizes, int n_in,
                              void* d_out, int out_size)
{
    const float* H    = (const float*)d_in[0];
    const int*   mask = (const int*)  d_in[1];
    const float* Wq   = (const float*)d_in[2];
    const float* bq   = (const float*)d_in[3];
    const float* Wk   = (const float*)d_in[4];
    const float* bk   = (const float*)d_in[5];
    const float* Wv   = (const float*)d_in[6];
    const float* bv   = (const float*)d_in[7];
    const float* Wo   = (const float*)d_in[8];
    const float* bo   = (const float*)d_in[9];

    float* out  = (float*)d_out;
    float* Aout = out + (size_t)Bq * Sq * Dm;

    const int smem1 = (128 * TS + 3 * 64 * TS) * sizeof(__half);            // 46080
    const int smem2 = (32 * PSH + 32 * TS + 2 * 128 * TS) * sizeof(__half)
                    + 32 * 32 * 4;                                          // 111616
    const int smem3 = 4 * 128 * TS * sizeof(__half);                        // 73728

    cudaFuncSetAttribute(qkv_kernel,  cudaFuncAttributeMaxDynamicSharedMemorySize, smem1);
    cudaFuncSetAttribute(attn_kernel, cudaFuncAttributeMaxDynamicSharedMemorySize, smem2);
    cudaFuncSetAttribute(out_kernel,  cudaFuncAttributeMaxDynamicSharedMemorySize, smem3);

    wconv_kernel<<<1024, 256>>>(Wo);
    hconv_kernel<<<8192, 256>>>(H);
    mpack_kernel<<<512, 256>>>(mask);
    qkv_kernel<<<dim3(64, NH), 256, smem1>>>(Wq, bq, Wk, bk, Wv, bv);
    attn_kernel<<<dim3(NH, 32, Bq), 256, smem2>>>(Aout);
    out_kernel<<<dim3(64, 8), 256, smem3>>>(bo, out);
}

// round 10
// speedup vs baseline: 1.1996x; 1.0158x over previous
#include <cuda_runtime.h>
#include <cuda_fp16.h>

#define Bq 8
#define Sq 1024
#define Dm 1024
#define NH 16
#define DH 64
#define NEGV (-1e9f)

#define PSH 1032   // half score/P row stride (2064B: +4 banks/row, LDSM conflict-free)
#define TS  72     // half tile row stride (144B: +4 banks/row)

// ---- scratch (device globals: allocation-free rule) ----
__device__ __half g_Hh[(size_t)Bq*Sq*Dm];
__device__ __half g_Q[(size_t)Bq*NH*Sq*DH];
__device__ __half g_K[(size_t)Bq*NH*Sq*DH];
__device__ __half g_V[(size_t)Bq*NH*Sq*DH];
__device__ __half g_heads[(size_t)Bq*Sq*Dm];
__device__ __half g_Woh[(size_t)Dm*Dm];

// ---- helpers ----
__device__ __forceinline__ void mma_f16(float c[4], const unsigned a[4],
                                        unsigned b0, unsigned b1) {
    asm volatile(
        "mma.sync.aligned.m16n8k16.row.col.f32.f16.f16.f32 "
        "{%0,%1,%2,%3}, {%4,%5,%6,%7}, {%8,%9}, {%0,%1,%2,%3};"
        : "+f"(c[0]), "+f"(c[1]), "+f"(c[2]), "+f"(c[3])
        : "r"(a[0]), "r"(a[1]), "r"(a[2]), "r"(a[3]), "r"(b0), "r"(b1));
}
__device__ __forceinline__ unsigned sptr(const void* p) {
    return (unsigned)__cvta_generic_to_shared(p);
}
__device__ __forceinline__ void ldm_x4(unsigned r[4], unsigned addr) {
    asm volatile("ldmatrix.sync.aligned.m8n8.x4.shared.b16 {%0,%1,%2,%3}, [%4];"
                 : "=r"(r[0]), "=r"(r[1]), "=r"(r[2]), "=r"(r[3]) : "r"(addr));
}
__device__ __forceinline__ void ldm_x4_t(unsigned r[4], unsigned addr) {
    asm volatile("ldmatrix.sync.aligned.m8n8.x4.trans.shared.b16 {%0,%1,%2,%3}, [%4];"
                 : "=r"(r[0]), "=r"(r[1]), "=r"(r[2]), "=r"(r[3]) : "r"(addr));
}
__device__ __forceinline__ void cpa16(unsigned dst, const void* src) {
    asm volatile("cp.async.cg.shared.global [%0], [%1], 16;" :: "r"(dst), "l"(src));
}
#define CPA_COMMIT() asm volatile("cp.async.commit_group;")
#define CPA_WAIT(n)  asm volatile("cp.async.wait_group %0;" :: "n"(n))

// ============================================================================
// K0a: Wo f32 -> half.  K0b: H f32 -> half.
// ============================================================================
__global__ void wconv_kernel(const float* __restrict__ Wo) {
    int i = (blockIdx.x * 256 + threadIdx.x) * 4;
    float4 v = *(const float4*)&Wo[i];
    __half2* dst = (__half2*)&g_Woh[i];
    dst[0] = __floats2half2_rn(v.x, v.y);
    dst[1] = __floats2half2_rn(v.z, v.w);
}
__global__ void hconv_kernel(const float* __restrict__ H) {
    int i = (blockIdx.x * 256 + threadIdx.x) * 4;
    float4 v = *(const float4*)&H[i];
    __half2* dst = (__half2*)&g_Hh[i];
    dst[0] = __floats2half2_rn(v.x, v.y);
    dst[1] = __floats2half2_rn(v.z, v.w);
}

// ============================================================================
// K1: fused QKV projection, fp16 mma + ldmatrix (measured 42us). grid (64, NH).
// ============================================================================
__global__ void __launch_bounds__(256) qkv_kernel(
    const float* __restrict__ Wq, const float* __restrict__ bq,
    const float* __restrict__ Wk, const float* __restrict__ bk,
    const float* __restrict__ Wv, const float* __restrict__ bv)
{
    extern __shared__ __half hsm[];
    __half* Hs = hsm;               // 128 x 72
    __half* Ws = hsm + 128 * TS;    // 3 x 64 x 72

    const int tid  = threadIdx.x;
    const int lane = tid & 31;
    const int warp = tid >> 5;
    const int g = lane >> 3, rr = lane & 7;
    const int warpM = warp >> 1;
    const int warpN = warp & 1;
    const int h    = blockIdx.y;
    const int row0 = blockIdx.x * 128;
    const int b    = row0 >> 10;
    const int s    = row0 & 1023;

    for (int i = tid; i < 128 * 8; i += 256) {
        int r = i >> 3, q = i & 7;
        cpa16(sptr(&Hs[r * TS + q * 8]),
              g_Hh + (size_t)(row0 + r) * Dm + h * DH + q * 8);
    }
    CPA_COMMIT();

    const float* Wt[3] = {Wq, Wk, Wv};
    for (int wsel = 0; wsel < 3; wsel++) {
        const float* W = Wt[wsel] + h * DH * DH;
        __half* Wd = Ws + wsel * 64 * TS;
        for (int i = tid; i < 64 * 16; i += 256) {
            int r = i >> 4, q = i & 15;
            float4 v = *(const float4*)&W[r * DH + q * 4];
            __half2* dst = (__half2*)&Wd[r * TS + q * 4];
            dst[0] = __floats2half2_rn(v.x, v.y);
            dst[1] = __floats2half2_rn(v.z, v.w);
        }
    }
    CPA_WAIT(0);
    __syncthreads();

    unsigned a[4][2][4];
    #pragma unroll
    for (int ks = 0; ks < 4; ks++)
        #pragma unroll
        for (int mi = 0; mi < 2; mi++) {
            int row = warpM * 32 + mi * 16 + rr + (g & 1) * 8;
            int col = ks * 16 + (g >> 1) * 8;
            ldm_x4(a[ks][mi], sptr(&Hs[row * TS + col]));
        }

    const float* bt[3] = {bq, bk, bv};
    __half*      Ot[3] = {g_Q, g_K, g_V};

    #pragma unroll
    for (int wsel = 0; wsel < 3; wsel++) {
        const __half* Wd = Ws + wsel * 64 * TS;
        float c[2][4][4];
        #pragma unroll
        for (int mi = 0; mi < 2; mi++)
            #pragma unroll
            for (int t = 0; t < 4; t++)
                #pragma unroll
                for (int q = 0; q < 4; q++) c[mi][t][q] = 0.f;

        #pragma unroll
        for (int ks = 0; ks < 4; ks++) {
            #pragma unroll
            for (int hn = 0; hn < 2; hn++) {
                int row = warpN * 32 + hn * 16 + rr + (g >> 1) * 8;
                int col = ks * 16 + (g & 1) * 8;
                unsigned bb[4];
                ldm_x4(bb, sptr(&Wd[row * TS + col]));
                #pragma unroll
                for (int mi = 0; mi < 2; mi++) {
                    mma_f16(c[mi][hn * 2 + 0], a[ks][mi], bb[0], bb[1]);
                    mma_f16(c[mi][hn * 2 + 1], a[ks][mi], bb[2], bb[3]);
                }
            }
        }

        const float* bias = bt[wsel] + h * DH;
        __half* O = Ot[wsel] + ((size_t)(b * NH + h) * Sq + s) * DH;
        #pragma unroll
        for (int mi = 0; mi < 2; mi++)
            #pragma unroll
            for (int t = 0; t < 4; t++) {
                int r  = warpM * 32 + mi * 16 + (lane >> 2);
                int cN = warpN * 32 + t * 8 + (lane & 3) * 2;
                float b0v = bias[cN], b1v = bias[cN + 1];
                *(__half2*)&O[(size_t)r * DH + cN] =
                    __floats2half2_rn(c[mi][t][0] + b0v, c[mi][t][1] + b1v);
                *(__half2*)&O[(size_t)(r + 8) * DH + cN] =
                    __floats2half2_rn(c[mi][t][2] + b0v, c[mi][t][3] + b1v);
            }
    }
}

// ============================================================================
// K2: attention — EXACT Round-3-benched version (measured 281us).
// 32 query rows, 256 thr / 8 warps. grid (NH, 32, Bq) h-fastest.
// ============================================================================
__global__ void __launch_bounds__(256) attn_kernel(
    const int* __restrict__ mask, float* __restrict__ Aout)
{
    extern __shared__ __half hsm[];
    __half* psh = hsm;                 // 32 x 1032 half: scores -> P
    __half* Qs  = psh + 32 * PSH;      // 32 x 72
    __half* KVs = Qs + 32 * TS;        // 2 x 128 x 72 (double buffer)

    const int tid = threadIdx.x, lane = tid & 31, warp = tid >> 5;
    const int h = blockIdx.x, b = blockIdx.z, s0 = blockIdx.y * 32;
    const int g = lane >> 3, rr = lane & 7;

    const __half* Qg = g_Q + ((size_t)(b * NH + h) * Sq + s0) * DH;
    const __half* Kg = g_K + (size_t)(b * NH + h) * Sq * DH;
    const __half* Vg = g_V + (size_t)(b * NH + h) * Sq * DH;

    // load Q tile 32x64
    for (int i = tid; i < 32 * 8; i += 256) {
        int r = i >> 3, q = i & 7;
        *(uint4*)&Qs[r * TS + q * 8] = ((const uint4*)Qg)[r * 8 + q];
    }

    const int warpM = warp >> 2;   // 0..1: 16 rows
    const int warpN = warp & 3;    // 0..3: 32 cols of 128-wide tile

    // issue K tile 0
    {
        for (int i = tid; i < 128 * 8; i += 256) {
            int r = i >> 3, q = i & 7;
            cpa16(sptr(&KVs[r * TS + q * 8]), Kg + (size_t)r * DH + q * 8);
        }
        CPA_COMMIT();
    }
    __syncthreads();

    // preload Q fragments (loop-invariant)
    unsigned qa[4][4];
    #pragma unroll
    for (int ks = 0; ks < 4; ks++) {
        int row = warpM * 16 + rr + (g & 1) * 8;
        int col = ks * 16 + (g >> 1) * 8;
        ldm_x4(qa[ks], sptr(&Qs[row * TS + col]));
    }

    // ---- Phase A: scores = Q K^T / 8 -> half smem ----
    for (int kt = 0; kt < 8; kt++) {
        if (kt < 7) {
            __half* dst = KVs + ((kt + 1) & 1) * 128 * TS;
            const __half* src = Kg + (size_t)(kt + 1) * 128 * DH;
            for (int i = tid; i < 128 * 8; i += 256) {
                int r = i >> 3, q = i & 7;
                cpa16(sptr(&dst[r * TS + q * 8]), src + (size_t)r * DH + q * 8);
            }
            CPA_COMMIT();
            CPA_WAIT(1);
        } else {
            CPA_WAIT(0);
        }
        __syncthreads();
        const __half* Kt = KVs + (kt & 1) * 128 * TS;

        float c[4][4];
        #pragma unroll
        for (int t = 0; t < 4; t++)
            #pragma unroll
            for (int q = 0; q < 4; q++) c[t][q] = 0.f;

        #pragma unroll
        for (int ks = 0; ks < 4; ks++) {
            #pragma unroll
            for (int hn = 0; hn < 2; hn++) {
                int n0 = warpN * 32 + hn * 16;
                int row = n0 + rr + (g >> 1) * 8;
                int col = ks * 16 + (g & 1) * 8;
                unsigned bb[4];
                ldm_x4(bb, sptr(&Kt[row * TS + col]));
                mma_f16(c[hn * 2 + 0], qa[ks], bb[0], bb[1]);
                mma_f16(c[hn * 2 + 1], qa[ks], bb[2], bb[3]);
            }
        }
        int r = warpM * 16 + (lane >> 2);
        #pragma unroll
        for (int t = 0; t < 4; t++) {
            int cN = kt * 128 + warpN * 32 + t * 8 + (lane & 3) * 2;
            *(__half2*)&psh[r * PSH + cN] =
                __floats2half2_rn(c[t][0] * 0.125f, c[t][1] * 0.125f);
            *(__half2*)&psh[(r + 8) * PSH + cN] =
                __floats2half2_rn(c[t][2] * 0.125f, c[t][3] * 0.125f);
        }
        __syncthreads();
    }

    // ---- softmax: warp w owns rows 4w..4w+3; elems in registers ----
    #pragma unroll
    for (int ri = 0; ri < 4; ri++) {
        int r = warp * 4 + ri;
        const int* mrow = mask + ((size_t)b * Sq + s0 + r) * Sq;
        float sv[32];
        float mx = NEGV;
        #pragma unroll
        for (int t = 0; t < 32; t++) {
            int j = t * 32 + lane;
            float s = __half2float(psh[r * PSH + j]);
            s = (mrow[j] == 0) ? NEGV : s;
            sv[t] = s;
            mx = fmaxf(mx, s);
        }
        #pragma unroll
        for (int o = 16; o; o >>= 1) mx = fmaxf(mx, __shfl_xor_sync(~0u, mx, o));
        float sum = 0.f;
        #pragma unroll
        for (int t = 0; t < 32; t++) {
            float e = __expf(sv[t] - mx);
            sv[t] = e;
            sum += e;
        }
        #pragma unroll
        for (int o = 16; o; o >>= 1) sum += __shfl_xor_sync(~0u, sum, o);
        float inv = 1.0f / sum;
        float* Ar = Aout + (((size_t)h * Bq + b) * Sq + s0 + r) * Sq;
        #pragma unroll
        for (int t = 0; t < 32; t++) {
            int j = t * 32 + lane;
            float a = sv[t] * inv;
            __stcs(&Ar[j], a);                       // streaming: keep L2 for K/V/mask
            psh[r * PSH + j] = __float2half_rn(a);   // normalized P in place
        }
    }

    // issue V tile 0
    {
        for (int i = tid; i < 128 * 8; i += 256) {
            int r = i >> 3, q = i & 7;
            cpa16(sptr(&KVs[r * TS + q * 8]), Vg + (size_t)r * DH + q * 8);
        }
        CPA_COMMIT();
    }

    // ---- Phase B: heads(32x64) = P @ V ----
    float c2[2][4];
    #pragma unroll
    for (int t = 0; t < 2; t++)
        #pragma unroll
        for (int q = 0; q < 4; q++) c2[t][q] = 0.f;

    const int n0 = warpN * 16;
    for (int kt = 0; kt < 8; kt++) {
        if (kt < 7) {
            __half* dst = KVs + ((kt + 1) & 1) * 128 * TS;
            const __half* src = Vg + (size_t)(kt + 1) * 128 * DH;
            for (int i = tid; i < 128 * 8; i += 256) {
                int r = i >> 3, q = i & 7;
                cpa16(sptr(&dst[r * TS + q * 8]), src + (size_t)r * DH + q * 8);
            }
            CPA_COMMIT();
            CPA_WAIT(1);
        } else {
            CPA_WAIT(0);
        }
        __syncthreads();
        const __half* Vt = KVs + (kt & 1) * 128 * TS;

        #pragma unroll
        for (int k0 = 0; k0 < 128; k0 += 16) {
            unsigned a[4];
            int arow = warpM * 16 + rr + (g & 1) * 8;
            int acol = kt * 128 + k0 + (g >> 1) * 8;
            ldm_x4(a, sptr(&psh[arow * PSH + acol]));
            unsigned bb[4];
            int brow = k0 + rr + (g & 1) * 8;
            int bcol = n0 + (g >> 1) * 8;
            ldm_x4_t(bb, sptr(&Vt[brow * TS + bcol]));
            mma_f16(c2[0], a, bb[0], bb[1]);
            mma_f16(c2[1], a, bb[2], bb[3]);
        }
        __syncthreads();
    }

    {
        int r = warpM * 16 + (lane >> 2);
        size_t base = ((size_t)(b * Sq + s0)) * Dm + h * DH;
        #pragma unroll
        for (int t = 0; t < 2; t++) {
            int cN = n0 + t * 8 + (lane & 3) * 2;
            *(__half2*)&g_heads[base + (size_t)r * Dm + cN] =
                __floats2half2_rn(c2[t][0], c2[t][1]);
            *(__half2*)&g_heads[base + (size_t)(r + 8) * Dm + cN] =
                __floats2half2_rn(c2[t][2], c2[t][3]);
        }
    }
}

// ============================================================================
// K3: out = heads @ Woh^T + bo. fp16 mma, tile 128x128, cp.async 2-stage.
// grid (64, 8), 256 thr.
// ============================================================================
__global__ void __launch_bounds__(256) out_kernel(
    const float* __restrict__ bo, float* __restrict__ out)
{
    extern __shared__ __half hsm[];
    __half* As = hsm;                  // 2 x 128 x 72
    __half* Bs = hsm + 2 * 128 * TS;   // 2 x 128 x 72

    const int tid = threadIdx.x, lane = tid & 31, warp = tid >> 5;
    const int g = lane >> 3, rr = lane & 7;
    const int warpM = warp >> 2;
    const int warpN = warp & 3;
    const int r0 = blockIdx.x * 128, n0 = blockIdx.y * 128;

    auto issue = [&](int kt, int buf) {
        __half* ad = As + buf * 128 * TS;
        __half* bd = Bs + buf * 128 * TS;
        const __half* as = g_heads + (size_t)r0 * Dm + kt * 64;
        const __half* bs = g_Woh   + (size_t)n0 * Dm + kt * 64;
        for (int i = tid; i < 128 * 8; i += 256) {
            int r = i >> 3, q = i & 7;
            cpa16(sptr(&ad[r * TS + q * 8]), as + (size_t)r * Dm + q * 8);
        }
        for (int i = tid; i < 128 * 8; i += 256) {
            int r = i >> 3, q = i & 7;
            cpa16(sptr(&bd[r * TS + q * 8]), bs + (size_t)r * Dm + q * 8);
        }
        CPA_COMMIT();
    };

    float c[4][4][4];
    #pragma unroll
    for (int mi = 0; mi < 4; mi++)
        #pragma unroll
        for (int nt = 0; nt < 4; nt++)
            #pragma unroll
            for (int q = 0; q < 4; q++) c[mi][nt][q] = 0.f;

    issue(0, 0);

    for (int kt = 0; kt < 16; kt++) {
        if (kt < 15) { issue(kt + 1, (kt + 1) & 1); CPA_WAIT(1); }
        else         { CPA_WAIT(0); }
        __syncthreads();
        const __half* At = As + (kt & 1) * 128 * TS;
        const __half* Bt = Bs + (kt & 1) * 128 * TS;

        #pragma unroll
        for (int ks = 0; ks < 4; ks++) {
            int k0 = ks * 16;
            unsigned a[4][4];
            #pragma unroll
            for (int mi = 0; mi < 4; mi++) {
                int row = warpM * 64 + mi * 16 + rr + (g & 1) * 8;
                int col = k0 + (g >> 1) * 8;
                ldm_x4(a[mi], sptr(&At[row * TS + col]));
            }
            unsigned bb[2][4];
            #pragma unroll
            for (int hn = 0; hn < 2; hn++) {
                int row = warpN * 32 + hn * 16 + rr + (g >> 1) * 8;
                int col = k0 + (g & 1) * 8;
                ldm_x4(bb[hn], sptr(&Bt[row * TS + col]));
            }
            #pragma unroll
            for (int mi = 0; mi < 4; mi++) {
                mma_f16(c[mi][0], a[mi], bb[0][0], bb[0][1]);
                mma_f16(c[mi][1], a[mi], bb[0][2], bb[0][3]);
                mma_f16(c[mi][2], a[mi], bb[1][0], bb[1][1]);
                mma_f16(c[mi][3], a[mi], bb[1][2], bb[1][3]);
            }
        }
        __syncthreads();
    }

    #pragma unroll
    for (int mi = 0; mi < 4; mi++) {
        #pragma unroll
        for (int nt = 0; nt < 4; nt++) {
            int r  = r0 + warpM * 64 + mi * 16 + (lane >> 2);
            int cN = n0 + warpN * 32 + nt * 8 + (lane & 3) * 2;
            float b0v = bo[cN], b1v = bo[cN + 1];
            out[(size_t)r * Dm + cN]           = c[mi][nt][0] + b0v;
            out[(size_t)r * Dm + cN + 1]       = c[mi][nt][1] + b1v;
            out[(size_t)(r + 8) * Dm + cN]     = c[mi][nt][2] + b0v;
            out[(size_t)(r + 8) * Dm + cN + 1] = c[mi][nt][3] + b1v;
        }
    }
}

// ============================================================================
extern "C" void kernel_launch(void* const* d_in, const int* in_sizes, int n_in,
                              void* d_out, int out_size)
{
    const float* H    = (const float*)d_in[0];
    const int*   mask = (const int*)  d_in[1];
    const float* Wq   = (const float*)d_in[2];
    const float* bq   = (const float*)d_in[3];
    const float* Wk   = (const float*)d_in[4];
    const float* bk   = (const float*)d_in[5];
    const float* Wv   = (const float*)d_in[6];
    const float* bv   = (const float*)d_in[7];
    const float* Wo   = (const float*)d_in[8];
    const float* bo   = (const float*)d_in[9];

    float* out  = (float*)d_out;
    float* Aout = out + (size_t)Bq * Sq * Dm;

    const int smem1 = (128 * TS + 3 * 64 * TS) * sizeof(__half);              // 46080
    const int smem2 = (32 * PSH + 32 * TS + 2 * 128 * TS) * sizeof(__half);   // 107520
    const int smem3 = 4 * 128 * TS * sizeof(__half);                          // 73728

    cudaFuncSetAttribute(qkv_kernel,  cudaFuncAttributeMaxDynamicSharedMemorySize, smem1);
    cudaFuncSetAttribute(attn_kernel, cudaFuncAttributeMaxDynamicSharedMemorySize, smem2);
    cudaFuncSetAttribute(out_kernel,  cudaFuncAttributeMaxDynamicSharedMemorySize, smem3);

    wconv_kernel<<<1024, 256>>>(Wo);
    hconv_kernel<<<8192, 256>>>(H);
    qkv_kernel<<<dim3(64, NH), 256, smem1>>>(Wq, bq, Wk, bk, Wv, bv);
    attn_kernel<<<dim3(NH, 32, Bq), 256, smem2>>>(mask, Aout);
    out_kernel<<<dim3(64, 8), 256, smem3>>>(bo, out);
}

// round 11
// speedup vs baseline: 1.2531x; 1.0446x over previous
#include <cuda_runtime.h>
#include <cuda_fp16.h>

#define Bq 8
#define Sq 1024
#define Dm 1024
#define NH 16
#define DH 64
#define NEGV (-1e9f)

#define PSH 1032   // half score/P row stride (2064B: +4 banks/row, LDSM conflict-free)
#define TS  72     // half tile row stride (144B: +4 banks/row)

// ---- scratch (device globals: allocation-free rule) ----
__device__ __half g_Hh[(size_t)Bq*Sq*Dm];
__device__ __half g_Q[(size_t)Bq*NH*Sq*DH];
__device__ __half g_K[(size_t)Bq*NH*Sq*DH];
__device__ __half g_V[(size_t)Bq*NH*Sq*DH];
__device__ __half g_heads[(size_t)Bq*Sq*Dm];
__device__ __half g_Woh[(size_t)Dm*Dm];

// ---- helpers ----
__device__ __forceinline__ void mma_f16(float c[4], const unsigned a[4],
                                        unsigned b0, unsigned b1) {
    asm volatile(
        "mma.sync.aligned.m16n8k16.row.col.f32.f16.f16.f32 "
        "{%0,%1,%2,%3}, {%4,%5,%6,%7}, {%8,%9}, {%0,%1,%2,%3};"
        : "+f"(c[0]), "+f"(c[1]), "+f"(c[2]), "+f"(c[3])
        : "r"(a[0]), "r"(a[1]), "r"(a[2]), "r"(a[3]), "r"(b0), "r"(b1));
}
__device__ __forceinline__ unsigned sptr(const void* p) {
    return (unsigned)__cvta_generic_to_shared(p);
}
__device__ __forceinline__ void ldm_x4(unsigned r[4], unsigned addr) {
    asm volatile("ldmatrix.sync.aligned.m8n8.x4.shared.b16 {%0,%1,%2,%3}, [%4];"
                 : "=r"(r[0]), "=r"(r[1]), "=r"(r[2]), "=r"(r[3]) : "r"(addr));
}
__device__ __forceinline__ void ldm_x4_t(unsigned r[4], unsigned addr) {
    asm volatile("ldmatrix.sync.aligned.m8n8.x4.trans.shared.b16 {%0,%1,%2,%3}, [%4];"
                 : "=r"(r[0]), "=r"(r[1]), "=r"(r[2]), "=r"(r[3]) : "r"(addr));
}
__device__ __forceinline__ void cpa16(unsigned dst, const void* src) {
    asm volatile("cp.async.cg.shared.global [%0], [%1], 16;" :: "r"(dst), "l"(src));
}
#define CPA_COMMIT() asm volatile("cp.async.commit_group;")
#define CPA_WAIT(n)  asm volatile("cp.async.wait_group %0;" :: "n"(n))

// ============================================================================
// K0a: Wo f32 -> half.  K0b: H f32 -> half.
// ============================================================================
__global__ void wconv_kernel(const float* __restrict__ Wo) {
    int i = (blockIdx.x * 256 + threadIdx.x) * 4;
    float4 v = *(const float4*)&Wo[i];
    __half2* dst = (__half2*)&g_Woh[i];
    dst[0] = __floats2half2_rn(v.x, v.y);
    dst[1] = __floats2half2_rn(v.z, v.w);
}
__global__ void hconv_kernel(const float* __restrict__ H) {
    int i = (blockIdx.x * 256 + threadIdx.x) * 4;
    float4 v = *(const float4*)&H[i];
    __half2* dst = (__half2*)&g_Hh[i];
    dst[0] = __floats2half2_rn(v.x, v.y);
    dst[1] = __floats2half2_rn(v.z, v.w);
}

// ============================================================================
// K1: fused QKV projection, fp16 mma + ldmatrix (measured 42us). grid (64, NH).
// ============================================================================
__global__ void __launch_bounds__(256) qkv_kernel(
    const float* __restrict__ Wq, const float* __restrict__ bq,
    const float* __restrict__ Wk, const float* __restrict__ bk,
    const float* __restrict__ Wv, const float* __restrict__ bv)
{
    extern __shared__ __half hsm[];
    __half* Hs = hsm;               // 128 x 72
    __half* Ws = hsm + 128 * TS;    // 3 x 64 x 72

    const int tid  = threadIdx.x;
    const int lane = tid & 31;
    const int warp = tid >> 5;
    const int g = lane >> 3, rr = lane & 7;
    const int warpM = warp >> 1;
    const int warpN = warp & 1;
    const int h    = blockIdx.y;
    const int row0 = blockIdx.x * 128;
    const int b    = row0 >> 10;
    const int s    = row0 & 1023;

    for (int i = tid; i < 128 * 8; i += 256) {
        int r = i >> 3, q = i & 7;
        cpa16(sptr(&Hs[r * TS + q * 8]),
              g_Hh + (size_t)(row0 + r) * Dm + h * DH + q * 8);
    }
    CPA_COMMIT();

    const float* Wt[3] = {Wq, Wk, Wv};
    for (int wsel = 0; wsel < 3; wsel++) {
        const float* W = Wt[wsel] + h * DH * DH;
        __half* Wd = Ws + wsel * 64 * TS;
        for (int i = tid; i < 64 * 16; i += 256) {
            int r = i >> 4, q = i & 15;
            float4 v = *(const float4*)&W[r * DH + q * 4];
            __half2* dst = (__half2*)&Wd[r * TS + q * 4];
            dst[0] = __floats2half2_rn(v.x, v.y);
            dst[1] = __floats2half2_rn(v.z, v.w);
        }
    }
    CPA_WAIT(0);
    __syncthreads();

    unsigned a[4][2][4];
    #pragma unroll
    for (int ks = 0; ks < 4; ks++)
        #pragma unroll
        for (int mi = 0; mi < 2; mi++) {
            int row = warpM * 32 + mi * 16 + rr + (g & 1) * 8;
            int col = ks * 16 + (g >> 1) * 8;
            ldm_x4(a[ks][mi], sptr(&Hs[row * TS + col]));
        }

    const float* bt[3] = {bq, bk, bv};
    __half*      Ot[3] = {g_Q, g_K, g_V};

    #pragma unroll
    for (int wsel = 0; wsel < 3; wsel++) {
        const __half* Wd = Ws + wsel * 64 * TS;
        float c[2][4][4];
        #pragma unroll
        for (int mi = 0; mi < 2; mi++)
            #pragma unroll
            for (int t = 0; t < 4; t++)
                #pragma unroll
                for (int q = 0; q < 4; q++) c[mi][t][q] = 0.f;

        #pragma unroll
        for (int ks = 0; ks < 4; ks++) {
            #pragma unroll
            for (int hn = 0; hn < 2; hn++) {
                int row = warpN * 32 + hn * 16 + rr + (g >> 1) * 8;
                int col = ks * 16 + (g & 1) * 8;
                unsigned bb[4];
                ldm_x4(bb, sptr(&Wd[row * TS + col]));
                #pragma unroll
                for (int mi = 0; mi < 2; mi++) {
                    mma_f16(c[mi][hn * 2 + 0], a[ks][mi], bb[0], bb[1]);
                    mma_f16(c[mi][hn * 2 + 1], a[ks][mi], bb[2], bb[3]);
                }
            }
        }

        const float* bias = bt[wsel] + h * DH;
        __half* O = Ot[wsel] + ((size_t)(b * NH + h) * Sq + s) * DH;
        #pragma unroll
        for (int mi = 0; mi < 2; mi++)
            #pragma unroll
            for (int t = 0; t < 4; t++) {
                int r  = warpM * 32 + mi * 16 + (lane >> 2);
                int cN = warpN * 32 + t * 8 + (lane & 3) * 2;
                float b0v = bias[cN], b1v = bias[cN + 1];
                *(__half2*)&O[(size_t)r * DH + cN] =
                    __floats2half2_rn(c[mi][t][0] + b0v, c[mi][t][1] + b1v);
                *(__half2*)&O[(size_t)(r + 8) * DH + cN] =
                    __floats2half2_rn(c[mi][t][2] + b0v, c[mi][t][3] + b1v);
            }
    }
}

// ============================================================================
// K2: attention — R3 structure; launch_bounds(256,2) to stop sv[] spills;
// softmax sweeps vectorized (int4 mask, float4 A, uint2 psh). grid (NH,32,Bq).
// ============================================================================
__global__ void __launch_bounds__(256, 2) attn_kernel(
    const int* __restrict__ mask, float* __restrict__ Aout)
{
    extern __shared__ __half hsm[];
    __half* psh = hsm;                 // 32 x 1032 half: scores -> P
    __half* Qs  = psh + 32 * PSH;      // 32 x 72
    __half* KVs = Qs + 32 * TS;        // 2 x 128 x 72 (double buffer)

    const int tid = threadIdx.x, lane = tid & 31, warp = tid >> 5;
    const int h = blockIdx.x, b = blockIdx.z, s0 = blockIdx.y * 32;
    const int g = lane >> 3, rr = lane & 7;

    const __half* Qg = g_Q + ((size_t)(b * NH + h) * Sq + s0) * DH;
    const __half* Kg = g_K + (size_t)(b * NH + h) * Sq * DH;
    const __half* Vg = g_V + (size_t)(b * NH + h) * Sq * DH;

    // load Q tile 32x64
    for (int i = tid; i < 32 * 8; i += 256) {
        int r = i >> 3, q = i & 7;
        *(uint4*)&Qs[r * TS + q * 8] = ((const uint4*)Qg)[r * 8 + q];
    }

    const int warpM = warp >> 2;   // 0..1: 16 rows
    const int warpN = warp & 3;    // 0..3: 32 cols of 128-wide tile

    // issue K tile 0
    {
        for (int i = tid; i < 128 * 8; i += 256) {
            int r = i >> 3, q = i & 7;
            cpa16(sptr(&KVs[r * TS + q * 8]), Kg + (size_t)r * DH + q * 8);
        }
        CPA_COMMIT();
    }
    __syncthreads();

    // preload Q fragments (loop-invariant)
    unsigned qa[4][4];
    #pragma unroll
    for (int ks = 0; ks < 4; ks++) {
        int row = warpM * 16 + rr + (g & 1) * 8;
        int col = ks * 16 + (g >> 1) * 8;
        ldm_x4(qa[ks], sptr(&Qs[row * TS + col]));
    }

    // ---- Phase A: scores = Q K^T / 8 -> half smem ----
    for (int kt = 0; kt < 8; kt++) {
        if (kt < 7) {
            __half* dst = KVs + ((kt + 1) & 1) * 128 * TS;
            const __half* src = Kg + (size_t)(kt + 1) * 128 * DH;
            for (int i = tid; i < 128 * 8; i += 256) {
                int r = i >> 3, q = i & 7;
                cpa16(sptr(&dst[r * TS + q * 8]), src + (size_t)r * DH + q * 8);
            }
            CPA_COMMIT();
            CPA_WAIT(1);
        } else {
            CPA_WAIT(0);
        }
        __syncthreads();
        const __half* Kt = KVs + (kt & 1) * 128 * TS;

        float c[4][4];
        #pragma unroll
        for (int t = 0; t < 4; t++)
            #pragma unroll
            for (int q = 0; q < 4; q++) c[t][q] = 0.f;

        #pragma unroll
        for (int ks = 0; ks < 4; ks++) {
            #pragma unroll
            for (int hn = 0; hn < 2; hn++) {
                int n0 = warpN * 32 + hn * 16;
                int row = n0 + rr + (g >> 1) * 8;
                int col = ks * 16 + (g & 1) * 8;
                unsigned bb[4];
                ldm_x4(bb, sptr(&Kt[row * TS + col]));
                mma_f16(c[hn * 2 + 0], qa[ks], bb[0], bb[1]);
                mma_f16(c[hn * 2 + 1], qa[ks], bb[2], bb[3]);
            }
        }
        int r = warpM * 16 + (lane >> 2);
        #pragma unroll
        for (int t = 0; t < 4; t++) {
            int cN = kt * 128 + warpN * 32 + t * 8 + (lane & 3) * 2;
            *(__half2*)&psh[r * PSH + cN] =
                __floats2half2_rn(c[t][0] * 0.125f, c[t][1] * 0.125f);
            *(__half2*)&psh[(r + 8) * PSH + cN] =
                __floats2half2_rn(c[t][2] * 0.125f, c[t][3] * 0.125f);
        }
        __syncthreads();
    }

    // ---- softmax: warp w owns rows 4w..4w+3; reg cache; vectorized sweeps ----
    #pragma unroll
    for (int ri = 0; ri < 4; ri++) {
        int r = warp * 4 + ri;
        const int4* mrow4 = (const int4*)(mask + ((size_t)b * Sq + s0 + r) * Sq);
        float sv[32];
        float mx = NEGV;
        #pragma unroll
        for (int t = 0; t < 8; t++) {
            int j = t * 128 + lane * 4;
            int4 m = mrow4[t * 32 + lane];
            uint2 pp = *(uint2*)&psh[r * PSH + j];
            __half2 p01 = *(__half2*)&pp.x, p23 = *(__half2*)&pp.y;
            float s0v = m.x ? __low2float(p01)  : NEGV;
            float s1v = m.y ? __high2float(p01) : NEGV;
            float s2v = m.z ? __low2float(p23)  : NEGV;
            float s3v = m.w ? __high2float(p23) : NEGV;
            sv[t * 4 + 0] = s0v; sv[t * 4 + 1] = s1v;
            sv[t * 4 + 2] = s2v; sv[t * 4 + 3] = s3v;
            mx = fmaxf(mx, fmaxf(fmaxf(s0v, s1v), fmaxf(s2v, s3v)));
        }
        #pragma unroll
        for (int o = 16; o; o >>= 1) mx = fmaxf(mx, __shfl_xor_sync(~0u, mx, o));
        float sum = 0.f;
        #pragma unroll
        for (int t = 0; t < 32; t++) {
            float e = __expf(sv[t] - mx);
            sv[t] = e;
            sum += e;
        }
        #pragma unroll
        for (int o = 16; o; o >>= 1) sum += __shfl_xor_sync(~0u, sum, o);
        float inv = 1.0f / sum;
        float4* Ar4 = (float4*)(Aout + (((size_t)h * Bq + b) * Sq + s0 + r) * Sq);
        #pragma unroll
        for (int t = 0; t < 8; t++) {
            int j = t * 128 + lane * 4;
            float a0 = sv[t * 4 + 0] * inv, a1 = sv[t * 4 + 1] * inv;
            float a2 = sv[t * 4 + 2] * inv, a3 = sv[t * 4 + 3] * inv;
            __stcs(&Ar4[t * 32 + lane], make_float4(a0, a1, a2, a3));
            __half2 h0 = __floats2half2_rn(a0, a1);
            __half2 h1 = __floats2half2_rn(a2, a3);
            uint2 st; st.x = *(unsigned*)&h0; st.y = *(unsigned*)&h1;
            *(uint2*)&psh[r * PSH + j] = st;
        }
    }

    // issue V tile 0
    {
        for (int i = tid; i < 128 * 8; i += 256) {
            int r = i >> 3, q = i & 7;
            cpa16(sptr(&KVs[r * TS + q * 8]), Vg + (size_t)r * DH + q * 8);
        }
        CPA_COMMIT();
    }

    // ---- Phase B: heads(32x64) = P @ V ----
    float c2[2][4];
    #pragma unroll
    for (int t = 0; t < 2; t++)
        #pragma unroll
        for (int q = 0; q < 4; q++) c2[t][q] = 0.f;

    const int n0 = warpN * 16;
    for (int kt = 0; kt < 8; kt++) {
        if (kt < 7) {
            __half* dst = KVs + ((kt + 1) & 1) * 128 * TS;
            const __half* src = Vg + (size_t)(kt + 1) * 128 * DH;
            for (int i = tid; i < 128 * 8; i += 256) {
                int r = i >> 3, q = i & 7;
                cpa16(sptr(&dst[r * TS + q * 8]), src + (size_t)r * DH + q * 8);
            }
            CPA_COMMIT();
            CPA_WAIT(1);
        } else {
            CPA_WAIT(0);
        }
        __syncthreads();
        const __half* Vt = KVs + (kt & 1) * 128 * TS;

        #pragma unroll
        for (int k0 = 0; k0 < 128; k0 += 16) {
            unsigned a[4];
            int arow = warpM * 16 + rr + (g & 1) * 8;
            int acol = kt * 128 + k0 + (g >> 1) * 8;
            ldm_x4(a, sptr(&psh[arow * PSH + acol]));
            unsigned bb[4];
            int brow = k0 + rr + (g & 1) * 8;
            int bcol = n0 + (g >> 1) * 8;
            ldm_x4_t(bb, sptr(&Vt[brow * TS + bcol]));
            mma_f16(c2[0], a, bb[0], bb[1]);
            mma_f16(c2[1], a, bb[2], bb[3]);
        }
        __syncthreads();
    }

    {
        int r = warpM * 16 + (lane >> 2);
        size_t base = ((size_t)(b * Sq + s0)) * Dm + h * DH;
        #pragma unroll
        for (int t = 0; t < 2; t++) {
            int cN = n0 + t * 8 + (lane & 3) * 2;
            *(__half2*)&g_heads[base + (size_t)r * Dm + cN] =
                __floats2half2_rn(c2[t][0], c2[t][1]);
            *(__half2*)&g_heads[base + (size_t)(r + 8) * Dm + cN] =
                __floats2half2_rn(c2[t][2], c2[t][3]);
        }
    }
}

// ============================================================================
// K3: out = heads @ Woh^T + bo. fp16 mma, tile 128x128, cp.async 2-stage.
// grid (64, 8), 256 thr.
// ============================================================================
__global__ void __launch_bounds__(256) out_kernel(
    const float* __restrict__ bo, float* __restrict__ out)
{
    extern __shared__ __half hsm[];
    __half* As = hsm;                  // 2 x 128 x 72
    __half* Bs = hsm + 2 * 128 * TS;   // 2 x 128 x 72

    const int tid = threadIdx.x, lane = tid & 31, warp = tid >> 5;
    const int g = lane >> 3, rr = lane & 7;
    const int warpM = warp >> 2;
    const int warpN = warp & 3;
    const int r0 = blockIdx.x * 128, n0 = blockIdx.y * 128;

    auto issue = [&](int kt, int buf) {
        __half* ad = As + buf * 128 * TS;
        __half* bd = Bs + buf * 128 * TS;
        const __half* as = g_heads + (size_t)r0 * Dm + kt * 64;
        const __half* bs = g_Woh   + (size_t)n0 * Dm + kt * 64;
        for (int i = tid; i < 128 * 8; i += 256) {
            int r = i >> 3, q = i & 7;
            cpa16(sptr(&ad[r * TS + q * 8]), as + (size_t)r * Dm + q * 8);
        }
        for (int i = tid; i < 128 * 8; i += 256) {
            int r = i >> 3, q = i & 7;
            cpa16(sptr(&bd[r * TS + q * 8]), bs + (size_t)r * Dm + q * 8);
        }
        CPA_COMMIT();
    };

    float c[4][4][4];
    #pragma unroll
    for (int mi = 0; mi < 4; mi++)
        #pragma unroll
        for (int nt = 0; nt < 4; nt++)
            #pragma unroll
            for (int q = 0; q < 4; q++) c[mi][nt][q] = 0.f;

    issue(0, 0);

    for (int kt = 0; kt < 16; kt++) {
        if (kt < 15) { issue(kt + 1, (kt + 1) & 1); CPA_WAIT(1); }
        else         { CPA_WAIT(0); }
        __syncthreads();
        const __half* At = As + (kt & 1) * 128 * TS;
        const __half* Bt = Bs + (kt & 1) * 128 * TS;

        #pragma unroll
        for (int ks = 0; ks < 4; ks++) {
            int k0 = ks * 16;
            unsigned a[4][4];
            #pragma unroll
            for (int mi = 0; mi < 4; mi++) {
                int row = warpM * 64 + mi * 16 + rr + (g & 1) * 8;
                int col = k0 + (g >> 1) * 8;
                ldm_x4(a[mi], sptr(&At[row * TS + col]));
            }
            unsigned bb[2][4];
            #pragma unroll
            for (int hn = 0; hn < 2; hn++) {
                int row = warpN * 32 + hn * 16 + rr + (g >> 1) * 8;
                int col = k0 + (g & 1) * 8;
                ldm_x4(bb[hn], sptr(&Bt[row * TS + col]));
            }
            #pragma unroll
            for (int mi = 0; mi < 4; mi++) {
                mma_f16(c[mi][0], a[mi], bb[0][0], bb[0][1]);
                mma_f16(c[mi][1], a[mi], bb[0][2], bb[0][3]);
                mma_f16(c[mi][2], a[mi], bb[1][0], bb[1][1]);
                mma_f16(c[mi][3], a[mi], bb[1][2], bb[1][3]);
            }
        }
        __syncthreads();
    }

    #pragma unroll
    for (int mi = 0; mi < 4; mi++) {
        #pragma unroll
        for (int nt = 0; nt < 4; nt++) {
            int r  = r0 + warpM * 64 + mi * 16 + (lane >> 2);
            int cN = n0 + warpN * 32 + nt * 8 + (lane & 3) * 2;
            float b0v = bo[cN], b1v = bo[cN + 1];
            out[(size_t)r * Dm + cN]           = c[mi][nt][0] + b0v;
            out[(size_t)r * Dm + cN + 1]       = c[mi][nt][1] + b1v;
            out[(size_t)(r + 8) * Dm + cN]     = c[mi][nt][2] + b0v;
            out[(size_t)(r + 8) * Dm + cN + 1] = c[mi][nt][3] + b1v;
        }
    }
}

// ============================================================================
extern "C" void kernel_launch(void* const* d_in, const int* in_sizes, int n_in,
                              void* d_out, int out_size)
{
    const float* H    = (const float*)d_in[0];
    const int*   mask = (const int*)  d_in[1];
    const float* Wq   = (const float*)d_in[2];
    const float* bq   = (const float*)d_in[3];
    const float* Wk   = (const float*)d_in[4];
    const float* bk   = (const float*)d_in[5];
    const float* Wv   = (const float*)d_in[6];
    const float* bv   = (const float*)d_in[7];
    const float* Wo   = (const float*)d_in[8];
    const float* bo   = (const float*)d_in[9];

    float* out  = (float*)d_out;
    float* Aout = out + (size_t)Bq * Sq * Dm;

    const int smem1 = (128 * TS + 3 * 64 * TS) * sizeof(__half);              // 46080
    const int smem2 = (32 * PSH + 32 * TS + 2 * 128 * TS) * sizeof(__half);   // 107520
    const int smem3 = 4 * 128 * TS * sizeof(__half);                          // 73728

    cudaFuncSetAttribute(qkv_kernel,  cudaFuncAttributeMaxDynamicSharedMemorySize, smem1);
    cudaFuncSetAttribute(attn_kernel, cudaFuncAttributeMaxDynamicSharedMemorySize, smem2);
    cudaFuncSetAttribute(out_kernel,  cudaFuncAttributeMaxDynamicSharedMemorySize, smem3);

    wconv_kernel<<<1024, 256>>>(Wo);
    hconv_kernel<<<8192, 256>>>(H);
    qkv_kernel<<<dim3(64, NH), 256, smem1>>>(Wq, bq, Wk, bk, Wv, bv);
    attn_kernel<<<dim3(NH, 32, Bq), 256, smem2>>>(mask, Aout);
    out_kernel<<<dim3(64, 8), 256, smem3>>>(bo, out);
}

// round 14
// speedup vs baseline: 1.2809x; 1.0222x over previous
#include <cuda_runtime.h>
#include <cuda_fp16.h>

#define Bq 8
#define Sq 1024
#define Dm 1024
#define NH 16
#define DH 64
#define NEGV (-1e9f)

#define PSH 1032   // half score/P row stride (2064B: +4 banks/row, LDSM conflict-free)
#define TS  72     // half tile row stride (144B: +4 banks/row)

// ---- scratch (device globals: allocation-free rule) ----
__device__ __half g_Hh[(size_t)Bq*Sq*Dm];
__device__ __half g_Q[(size_t)Bq*NH*Sq*DH];
__device__ __half g_K[(size_t)Bq*NH*Sq*DH];
__device__ __half g_V[(size_t)Bq*NH*Sq*DH];
__device__ __half g_heads[(size_t)Bq*Sq*Dm];
__device__ __half g_Woh[(size_t)Dm*Dm];

// ---- helpers ----
__device__ __forceinline__ void mma_f16(float c[4], const unsigned a[4],
                                        unsigned b0, unsigned b1) {
    asm volatile(
        "mma.sync.aligned.m16n8k16.row.col.f32.f16.f16.f32 "
        "{%0,%1,%2,%3}, {%4,%5,%6,%7}, {%8,%9}, {%0,%1,%2,%3};"
        : "+f"(c[0]), "+f"(c[1]), "+f"(c[2]), "+f"(c[3])
        : "r"(a[0]), "r"(a[1]), "r"(a[2]), "r"(a[3]), "r"(b0), "r"(b1));
}
__device__ __forceinline__ unsigned sptr(const void* p) {
    return (unsigned)__cvta_generic_to_shared(p);
}
__device__ __forceinline__ void ldm_x4(unsigned r[4], unsigned addr) {
    asm volatile("ldmatrix.sync.aligned.m8n8.x4.shared.b16 {%0,%1,%2,%3}, [%4];"
                 : "=r"(r[0]), "=r"(r[1]), "=r"(r[2]), "=r"(r[3]) : "r"(addr));
}
__device__ __forceinline__ void ldm_x4_t(unsigned r[4], unsigned addr) {
    asm volatile("ldmatrix.sync.aligned.m8n8.x4.trans.shared.b16 {%0,%1,%2,%3}, [%4];"
                 : "=r"(r[0]), "=r"(r[1]), "=r"(r[2]), "=r"(r[3]) : "r"(addr));
}
__device__ __forceinline__ void cpa16(unsigned dst, const void* src) {
    asm volatile("cp.async.cg.shared.global [%0], [%1], 16;" :: "r"(dst), "l"(src));
}
#define CPA_COMMIT() asm volatile("cp.async.commit_group;")
#define CPA_WAIT(n)  asm volatile("cp.async.wait_group %0;" :: "n"(n))

// ============================================================================
// K0a: Wo f32 -> half.  K0b: H f32 -> half.
// ============================================================================
__global__ void wconv_kernel(const float* __restrict__ Wo) {
    int i = (blockIdx.x * 256 + threadIdx.x) * 4;
    float4 v = *(const float4*)&Wo[i];
    __half2* dst = (__half2*)&g_Woh[i];
    dst[0] = __floats2half2_rn(v.x, v.y);
    dst[1] = __floats2half2_rn(v.z, v.w);
}
__global__ void hconv_kernel(const float* __restrict__ H) {
    int i = (blockIdx.x * 256 + threadIdx.x) * 4;
    float4 v = *(const float4*)&H[i];
    __half2* dst = (__half2*)&g_Hh[i];
    dst[0] = __floats2half2_rn(v.x, v.y);
    dst[1] = __floats2half2_rn(v.z, v.w);
}

// ============================================================================
// K1: fused QKV projection, fp16 mma + ldmatrix (measured 42us). grid (64, NH).
// ============================================================================
__global__ void __launch_bounds__(256) qkv_kernel(
    const float* __restrict__ Wq, const float* __restrict__ bq,
    const float* __restrict__ Wk, const float* __restrict__ bk,
    const float* __restrict__ Wv, const float* __restrict__ bv)
{
    extern __shared__ __half hsm[];
    __half* Hs = hsm;               // 128 x 72
    __half* Ws = hsm + 128 * TS;    // 3 x 64 x 72

    const int tid  = threadIdx.x;
    const int lane = tid & 31;
    const int warp = tid >> 5;
    const int g = lane >> 3, rr = lane & 7;
    const int warpM = warp >> 1;
    const int warpN = warp & 1;
    const int h    = blockIdx.y;
    const int row0 = blockIdx.x * 128;
    const int b    = row0 >> 10;
    const int s    = row0 & 1023;

    for (int i = tid; i < 128 * 8; i += 256) {
        int r = i >> 3, q = i & 7;
        cpa16(sptr(&Hs[r * TS + q * 8]),
              g_Hh + (size_t)(row0 + r) * Dm + h * DH + q * 8);
    }
    CPA_COMMIT();

    const float* Wt[3] = {Wq, Wk, Wv};
    for (int wsel = 0; wsel < 3; wsel++) {
        const float* W = Wt[wsel] + h * DH * DH;
        __half* Wd = Ws + wsel * 64 * TS;
        for (int i = tid; i < 64 * 16; i += 256) {
            int r = i >> 4, q = i & 15;
            float4 v = *(const float4*)&W[r * DH + q * 4];
            __half2* dst = (__half2*)&Wd[r * TS + q * 4];
            dst[0] = __floats2half2_rn(v.x, v.y);
            dst[1] = __floats2half2_rn(v.z, v.w);
        }
    }
    CPA_WAIT(0);
    __syncthreads();

    unsigned a[4][2][4];
    #pragma unroll
    for (int ks = 0; ks < 4; ks++)
        #pragma unroll
        for (int mi = 0; mi < 2; mi++) {
            int row = warpM * 32 + mi * 16 + rr + (g & 1) * 8;
            int col = ks * 16 + (g >> 1) * 8;
            ldm_x4(a[ks][mi], sptr(&Hs[row * TS + col]));
        }

    const float* bt[3] = {bq, bk, bv};
    __half*      Ot[3] = {g_Q, g_K, g_V};

    #pragma unroll
    for (int wsel = 0; wsel < 3; wsel++) {
        const __half* Wd = Ws + wsel * 64 * TS;
        float c[2][4][4];
        #pragma unroll
        for (int mi = 0; mi < 2; mi++)
            #pragma unroll
            for (int t = 0; t < 4; t++)
                #pragma unroll
                for (int q = 0; q < 4; q++) c[mi][t][q] = 0.f;

        #pragma unroll
        for (int ks = 0; ks < 4; ks++) {
            #pragma unroll
            for (int hn = 0; hn < 2; hn++) {
                int row = warpN * 32 + hn * 16 + rr + (g >> 1) * 8;
                int col = ks * 16 + (g & 1) * 8;
                unsigned bb[4];
                ldm_x4(bb, sptr(&Wd[row * TS + col]));
                #pragma unroll
                for (int mi = 0; mi < 2; mi++) {
                    mma_f16(c[mi][hn * 2 + 0], a[ks][mi], bb[0], bb[1]);
                    mma_f16(c[mi][hn * 2 + 1], a[ks][mi], bb[2], bb[3]);
                }
            }
        }

        const float* bias = bt[wsel] + h * DH;
        __half* O = Ot[wsel] + ((size_t)(b * NH + h) * Sq + s) * DH;
        #pragma unroll
        for (int mi = 0; mi < 2; mi++)
            #pragma unroll
            for (int t = 0; t < 4; t++) {
                int r  = warpM * 32 + mi * 16 + (lane >> 2);
                int cN = warpN * 32 + t * 8 + (lane & 3) * 2;
                float b0v = bias[cN], b1v = bias[cN + 1];
                *(__half2*)&O[(size_t)r * DH + cN] =
                    __floats2half2_rn(c[mi][t][0] + b0v, c[mi][t][1] + b1v);
                *(__half2*)&O[(size_t)(r + 8) * DH + cN] =
                    __floats2half2_rn(c[mi][t][2] + b0v, c[mi][t][3] + b1v);
            }
    }
}

// ============================================================================
// K2: attention — R3 skeleton; phase-A warp re-tile (32 rows x 16 keys/warp,
// B-LDSM halved); single-barrier cp.async pipelining in both phases.
// grid (NH, 32, Bq), 256 thr, launch_bounds(256,2).
// ============================================================================
__global__ void __launch_bounds__(256, 2) attn_kernel(
    const int* __restrict__ mask, float* __restrict__ Aout)
{
    extern __shared__ __half hsm[];
    __half* psh = hsm;                 // 32 x 1032 half: scores -> P
    __half* Qs  = psh + 32 * PSH;      // 32 x 72
    __half* KVs = Qs + 32 * TS;        // 2 x 128 x 72 (double buffer)

    const int tid = threadIdx.x, lane = tid & 31, warp = tid >> 5;
    const int h = blockIdx.x, b = blockIdx.z, s0 = blockIdx.y * 32;
    const int g = lane >> 3, rr = lane & 7;

    const __half* Qg = g_Q + ((size_t)(b * NH + h) * Sq + s0) * DH;
    const __half* Kg = g_K + (size_t)(b * NH + h) * Sq * DH;
    const __half* Vg = g_V + (size_t)(b * NH + h) * Sq * DH;

    auto issue = [&](const __half* src, int buf) {
        __half* dst = KVs + buf * 128 * TS;
        for (int i = tid; i < 128 * 8; i += 256) {
            int r = i >> 3, q = i & 7;
            cpa16(sptr(&dst[r * TS + q * 8]), src + (size_t)r * DH + q * 8);
        }
        CPA_COMMIT();
    };

    issue(Kg, 0);
    // load Q tile 32x64
    for (int i = tid; i < 32 * 8; i += 256) {
        int r = i >> 3, q = i & 7;
        *(uint4*)&Qs[r * TS + q * 8] = ((const uint4*)Qg)[r * 8 + q];
    }
    __syncthreads();

    // preload Q fragments for BOTH 16-row halves (loop-invariant)
    unsigned qa[4][2][4];
    #pragma unroll
    for (int ks = 0; ks < 4; ks++)
        #pragma unroll
        for (int mi = 0; mi < 2; mi++) {
            int row = mi * 16 + rr + (g & 1) * 8;
            int col = ks * 16 + (g >> 1) * 8;
            ldm_x4(qa[ks][mi], sptr(&Qs[row * TS + col]));
        }

    const int wn = warp;   // phase A: warp owns keys wn*16 .. wn*16+15, all 32 rows

    // ---- Phase A: scores = Q K^T / 8 -> half smem (single sync per tile) ----
    for (int kt = 0; kt < 8; kt++) {
        CPA_WAIT(0);
        __syncthreads();
        if (kt < 7) issue(Kg + (size_t)(kt + 1) * 128 * DH, (kt + 1) & 1);
        const __half* Kt = KVs + (kt & 1) * 128 * TS;

        float c[2][2][4];
        #pragma unroll
        for (int mi = 0; mi < 2; mi++)
            #pragma unroll
            for (int t = 0; t < 2; t++)
                #pragma unroll
                for (int q = 0; q < 4; q++) c[mi][t][q] = 0.f;

        #pragma unroll
        for (int ks = 0; ks < 4; ks++) {
            unsigned bb[4];
            ldm_x4(bb, sptr(&Kt[(wn * 16 + rr + (g >> 1) * 8) * TS +
                                ks * 16 + (g & 1) * 8]));
            #pragma unroll
            for (int mi = 0; mi < 2; mi++) {
                mma_f16(c[mi][0], qa[ks][mi], bb[0], bb[1]);
                mma_f16(c[mi][1], qa[ks][mi], bb[2], bb[3]);
            }
        }
        int rq = lane >> 2;
        #pragma unroll
        for (int mi = 0; mi < 2; mi++)
            #pragma unroll
            for (int t = 0; t < 2; t++) {
                int cN = kt * 128 + wn * 16 + t * 8 + (lane & 3) * 2;
                *(__half2*)&psh[(mi * 16 + rq) * PSH + cN] =
                    __floats2half2_rn(c[mi][t][0] * 0.125f, c[mi][t][1] * 0.125f);
                *(__half2*)&psh[(mi * 16 + rq + 8) * PSH + cN] =
                    __floats2half2_rn(c[mi][t][2] * 0.125f, c[mi][t][3] * 0.125f);
            }
    }
    __syncthreads();   // psh complete (cross-warp) before softmax

    issue(Vg, 0);      // overlap V tile 0 with softmax (K bufs idle now)

    // ---- softmax: warp w owns rows 4w..4w+3; reg cache; vectorized sweeps ----
    #pragma unroll
    for (int ri = 0; ri < 4; ri++) {
        int r = warp * 4 + ri;
        const int4* mrow4 = (const int4*)(mask + ((size_t)b * Sq + s0 + r) * Sq);
        float sv[32];
        float mx = NEGV;
        #pragma unroll
        for (int t = 0; t < 8; t++) {
            int j = t * 128 + lane * 4;
            int4 m = mrow4[t * 32 + lane];
            uint2 pp = *(uint2*)&psh[r * PSH + j];
            __half2 p01 = *(__half2*)&pp.x, p23 = *(__half2*)&pp.y;
            float s0v = m.x ? __low2float(p01)  : NEGV;
            float s1v = m.y ? __high2float(p01) : NEGV;
            float s2v = m.z ? __low2float(p23)  : NEGV;
            float s3v = m.w ? __high2float(p23) : NEGV;
            sv[t * 4 + 0] = s0v; sv[t * 4 + 1] = s1v;
            sv[t * 4 + 2] = s2v; sv[t * 4 + 3] = s3v;
            mx = fmaxf(mx, fmaxf(fmaxf(s0v, s1v), fmaxf(s2v, s3v)));
        }
        #pragma unroll
        for (int o = 16; o; o >>= 1) mx = fmaxf(mx, __shfl_xor_sync(~0u, mx, o));
        float sum = 0.f;
        #pragma unroll
        for (int t = 0; t < 32; t++) {
            float e = __expf(sv[t] - mx);
            sv[t] = e;
            sum += e;
        }
        #pragma unroll
        for (int o = 16; o; o >>= 1) sum += __shfl_xor_sync(~0u, sum, o);
        float inv = 1.0f / sum;
        float4* Ar4 = (float4*)(Aout + (((size_t)h * Bq + b) * Sq + s0 + r) * Sq);
        #pragma unroll
        for (int t = 0; t < 8; t++) {
            int j = t * 128 + lane * 4;
            float a0 = sv[t * 4 + 0] * inv, a1 = sv[t * 4 + 1] * inv;
            float a2 = sv[t * 4 + 2] * inv, a3 = sv[t * 4 + 3] * inv;
            __stcs(&Ar4[t * 32 + lane], make_float4(a0, a1, a2, a3));
            __half2 h0 = __floats2half2_rn(a0, a1);
            __half2 h1 = __floats2half2_rn(a2, a3);
            uint2 st; st.x = *(unsigned*)&h0; st.y = *(unsigned*)&h1;
            *(uint2*)&psh[r * PSH + j] = st;
        }
    }

    // ---- Phase B: heads(32x64) = P @ V (single sync per tile) ----
    float c2[2][4];
    #pragma unroll
    for (int t = 0; t < 2; t++)
        #pragma unroll
        for (int q = 0; q < 4; q++) c2[t][q] = 0.f;

    const int warpM = warp >> 2;   // 0..1: 16 rows
    const int warpN = warp & 3;    // 0..3: 16 head-cols
    const int n0 = warpN * 16;

    for (int kt = 0; kt < 8; kt++) {
        CPA_WAIT(0);
        __syncthreads();   // iter0 also publishes softmax psh writes to all warps
        if (kt < 7) issue(Vg + (size_t)(kt + 1) * 128 * DH, (kt + 1) & 1);
        const __half* Vt = KVs + (kt & 1) * 128 * TS;

        #pragma unroll
        for (int k0 = 0; k0 < 128; k0 += 16) {
            unsigned a[4];
            int arow = warpM * 16 + rr + (g & 1) * 8;
            int acol = kt * 128 + k0 + (g >> 1) * 8;
            ldm_x4(a, sptr(&psh[arow * PSH + acol]));
            unsigned bb[4];
            int brow = k0 + rr + (g & 1) * 8;
            int bcol = n0 + (g >> 1) * 8;
            ldm_x4_t(bb, sptr(&Vt[brow * TS + bcol]));
            mma_f16(c2[0], a, bb[0], bb[1]);
            mma_f16(c2[1], a, bb[2], bb[3]);
        }
    }

    {
        int r = warpM * 16 + (lane >> 2);
        size_t base = ((size_t)(b * Sq + s0)) * Dm + h * DH;
        #pragma unroll
        for (int t = 0; t < 2; t++) {
            int cN = n0 + t * 8 + (lane & 3) * 2;
            *(__half2*)&g_heads[base + (size_t)r * Dm + cN] =
                __floats2half2_rn(c2[t][0], c2[t][1]);
            *(__half2*)&g_heads[base + (size_t)(r + 8) * Dm + cN] =
                __floats2half2_rn(c2[t][2], c2[t][3]);
        }
    }
}

// ============================================================================
// K3: out = heads @ Woh^T + bo. fp16 mma, tile 128x128, cp.async 2-stage,
// single sync per tile. grid (64, 8), 256 thr.
// ============================================================================
__global__ void __launch_bounds__(256) out_kernel(
    const float* __restrict__ bo, float* __restrict__ out)
{
    extern __shared__ __half hsm[];
    __half* As = hsm;                  // 2 x 128 x 72
    __half* Bs = hsm + 2 * 128 * TS;   // 2 x 128 x 72

    const int tid = threadIdx.x, lane = tid & 31, warp = tid >> 5;
    const int g = lane >> 3, rr = lane & 7;
    const int warpM = warp >> 2;
    const int warpN = warp & 3;
    const int r0 = blockIdx.x * 128, n0 = blockIdx.y * 128;

    auto issue = [&](int kt, int buf) {
        __half* ad = As + buf * 128 * TS;
        __half* bd = Bs + buf * 128 * TS;
        const __half* as = g_heads + (size_t)r0 * Dm + kt * 64;
        const __half* bs = g_Woh   + (size_t)n0 * Dm + kt * 64;
        for (int i = tid; i < 128 * 8; i += 256) {
            int r = i >> 3, q = i & 7;
            cpa16(sptr(&ad[r * TS + q * 8]), as + (size_t)r * Dm + q * 8);
        }
        for (int i = tid; i < 128 * 8; i += 256) {
            int r = i >> 3, q = i & 7;
            cpa16(sptr(&bd[r * TS + q * 8]), bs + (size_t)r * Dm + q * 8);
        }
        CPA_COMMIT();
    };

    float c[4][4][4];
    #pragma unroll
    for (int mi = 0; mi < 4; mi++)
        #pragma unroll
        for (int nt = 0; nt < 4; nt++)
            #pragma unroll
            for (int q = 0; q < 4; q++) c[mi][nt][q] = 0.f;

    issue(0, 0);

    for (int kt = 0; kt < 16; kt++) {
        CPA_WAIT(0);
        __syncthreads();
        if (kt < 15) issue(kt + 1, (kt + 1) & 1);
        const __half* At = As + (kt & 1) * 128 * TS;
        const __half* Bt = Bs + (kt & 1) * 128 * TS;

        #pragma unroll
        for (int ks = 0; ks < 4; ks++) {
            int k0 = ks * 16;
            unsigned a[4][4];
            #pragma unroll
            for (int mi = 0; mi < 4; mi++) {
                int row = warpM * 64 + mi * 16 + rr + (g & 1) * 8;
                int col = k0 + (g >> 1) * 8;
                ldm_x4(a[mi], sptr(&At[row * TS + col]));
            }
            unsigned bb[2][4];
            #pragma unroll
            for (int hn = 0; hn < 2; hn++) {
                int row = warpN * 32 + hn * 16 + rr + (g >> 1) * 8;
                int col = k0 + (g & 1) * 8;
                ldm_x4(bb[hn], sptr(&Bt[row * TS + col]));
            }
            #pragma unroll
            for (int mi = 0; mi < 4; mi++) {
                mma_f16(c[mi][0], a[mi], bb[0][0], bb[0][1]);
                mma_f16(c[mi][1], a[mi], bb[0][2], bb[0][3]);
                mma_f16(c[mi][2], a[mi], bb[1][0], bb[1][1]);
                mma_f16(c[mi][3], a[mi], bb[1][2], bb[1][3]);
            }
        }
    }

    #pragma unroll
    for (int mi = 0; mi < 4; mi++) {
        #pragma unroll
        for (int nt = 0; nt < 4; nt++) {
            int r  = r0 + warpM * 64 + mi * 16 + (lane >> 2);
            int cN = n0 + warpN * 32 + nt * 8 + (lane & 3) * 2;
            float b0v = bo[cN], b1v = bo[cN + 1];
            out[(size_t)r * Dm + cN]           = c[mi][nt][0] + b0v;
            out[(size_t)r * Dm + cN + 1]       = c[mi][nt][1] + b1v;
            out[(size_t)(r + 8) * Dm + cN]     = c[mi][nt][2] + b0v;
            out[(size_t)(r + 8) * Dm + cN + 1] = c[mi][nt][3] + b1v;
        }
    }
}

// ============================================================================
extern "C" void kernel_launch(void* const* d_in, const int* in_sizes, int n_in,
                              void* d_out, int out_size)
{
    const float* H    = (const float*)d_in[0];
    const int*   mask = (const int*)  d_in[1];
    const float* Wq   = (const float*)d_in[2];
    const float* bq   = (const float*)d_in[3];
    const float* Wk   = (const float*)d_in[4];
    const float* bk   = (const float*)d_in[5];
    const float* Wv   = (const float*)d_in[6];
    const float* bv   = (const float*)d_in[7];
    const float* Wo   = (const float*)d_in[8];
    const float* bo   = (const float*)d_in[9];

    float* out  = (float*)d_out;
    float* Aout = out + (size_t)Bq * Sq * Dm;

    const int smem1 = (128 * TS + 3 * 64 * TS) * sizeof(__half);              // 46080
    const int smem2 = (32 * PSH + 32 * TS + 2 * 128 * TS) * sizeof(__half);   // 107520
    const int smem3 = 4 * 128 * TS * sizeof(__half);                          // 73728

    cudaFuncSetAttribute(qkv_kernel,  cudaFuncAttributeMaxDynamicSharedMemorySize, smem1);
    cudaFuncSetAttribute(attn_kernel, cudaFuncAttributeMaxDynamicSharedMemorySize, smem2);
    cudaFuncSetAttribute(out_kernel,  cudaFuncAttributeMaxDynamicSharedMemorySize, smem3);

    wconv_kernel<<<1024, 256>>>(Wo);
    hconv_kernel<<<8192, 256>>>(H);
    qkv_kernel<<<dim3(64, NH), 256, smem1>>>(Wq, bq, Wk, bk, Wv, bv);
    attn_kernel<<<dim3(NH, 32, Bq), 256, smem2>>>(mask, Aout);
    out_kernel<<<dim3(64, 8), 256, smem3>>>(bo, out);
}